// round 4
// baseline (speedup 1.0000x reference)
#include <cuda_runtime.h>

// Kalman filter B=2048, T=64, STATE=32, OBS=16.
// Phase 1 (1 CTA): batch-independent Riccati recursion -> per-step W_t = [A_t^T ; K_t^T].
// Phase 2 (128 CTAs): per-batch linear recursion x_t = A_t x_{t-1} + K_t z_t.

#define SD 32
#define OD 16
#define TT 64
#define NB 2048
#define P32 33
#define P16 17

// W_t layout: rows 0..31: W[j][i] = A_t[i][j]; rows 32..47: W[32+o][i] = K_t[i][o]
__device__ __align__(16) float g_W[TT][48 * SD];

// ---------------------------------------------------------------------------
// Phase 1
// ---------------------------------------------------------------------------
__global__ void __launch_bounds__(256, 1) phase1_kernel(
    const float* __restrict__ Fg,
    const float* __restrict__ Hg,
    const float* __restrict__ Qg,
    const float* __restrict__ Rg,
    const float* __restrict__ cov0)
{
    __shared__ float Fs[SD * P32];   // F row-major
    __shared__ float FT[SD * P32];   // F^T: FT[j][i] = F[i][j]
    __shared__ float Qs[SD * P32];
    __shared__ float Hs[OD * P32];   // H row-major
    __shared__ float Rs[OD * P16];
    __shared__ float Gs[OD * P32];   // G = H@F row-major: Gs[o][j]
    __shared__ float Ps[SD * P32];   // filtered covariance
    __shared__ float Pp[SD * P32];   // predicted covariance
    __shared__ float T1[SD * P32];   // temp (general-F path only)
    __shared__ float HPs[OD * P32];  // H @ Pp
    __shared__ float aug[OD * 49];   // [S | HP]
    __shared__ float KTs[OD * P32];  // K^T: KTs[o][i] = K[i][o]
    __shared__ int fid;

    const int tid  = threadIdx.x;
    const int wid  = tid >> 5;
    const int lane = tid & 31;

    if (tid == 0) fid = 1;
    __syncthreads();

    {
        bool ok = true;
        #pragma unroll
        for (int s = 0; s < 4; s++) {
            int e = tid + s * 256;
            int i = e >> 5, j = e & 31;
            float f = Fg[e];
            Fs[i * P32 + j] = f;
            FT[j * P32 + i] = f;
            Qs[i * P32 + j] = Qg[e];
            Ps[i * P32 + j] = cov0[e];
            if (f != ((i == j) ? 1.0f : 0.0f)) ok = false;
        }
        if (!ok) fid = 0;
        #pragma unroll
        for (int s = 0; s < 2; s++) {
            int e = tid + s * 256;
            Hs[(e >> 5) * P32 + (e & 31)] = Hg[e];
        }
        Rs[(tid >> 4) * P16 + (tid & 15)] = Rg[tid];
    }
    __syncthreads();

    // G[o][j] = sum_k H[o][k] F[k][j]
    #pragma unroll
    for (int s = 0; s < 2; s++) {
        int e = tid + s * 256;
        int o = e >> 5, j = e & 31;
        float acc = 0.f;
        #pragma unroll
        for (int k = 0; k < SD; k++) acc += Hs[o * P32 + k] * FT[j * P32 + k];
        Gs[o * P32 + j] = acc;
    }
    const int ident = fid;
    __syncthreads();

    #pragma unroll 1
    for (int t = 0; t < TT; t++) {
        // ---- predict: Pp = F P F^T + Q ----
        if (ident) {
            #pragma unroll
            for (int s = 0; s < 4; s++) {
                int e = tid + s * 256;
                int idx = (e >> 5) * P32 + (e & 31);
                Pp[idx] = Ps[idx] + Qs[idx];
            }
        } else {
            #pragma unroll
            for (int s = 0; s < 4; s++) {
                int e = tid + s * 256;
                int i = e >> 5, j = e & 31;
                float acc = 0.f;
                #pragma unroll
                for (int k = 0; k < SD; k++) acc += Fs[i * P32 + k] * Ps[k * P32 + j];
                T1[i * P32 + j] = acc;
            }
            __syncthreads();
            #pragma unroll
            for (int s = 0; s < 4; s++) {
                int e = tid + s * 256;
                int i = e >> 5, j = e & 31;
                float acc = Qs[i * P32 + j];
                #pragma unroll
                for (int k = 0; k < SD; k++) acc += T1[i * P32 + k] * Fs[j * P32 + k];
                Pp[i * P32 + j] = acc;
            }
        }
        __syncthreads();

        // ---- HP[r][j] = sum_k H[r][k] Pp[k][j] ; rows r, r+8 share Pp loads ----
        {
            int r = wid;           // 0..7
            int j = lane;
            float a0 = 0.f, a1 = 0.f;
            #pragma unroll
            for (int k = 0; k < SD; k++) {
                float pv = Pp[k * P32 + j];            // lane stride-1
                a0 += Hs[r * P32 + k] * pv;            // broadcast
                a1 += Hs[(r + 8) * P32 + k] * pv;      // broadcast
            }
            HPs[r * P32 + j] = a0;
            HPs[(r + 8) * P32 + j] = a1;
        }
        __syncthreads();

        // ---- aug = [S | HP], S = HP H^T + R ----
        for (int e = tid; e < 768; e += 256) {
            int r = e / 48, c = e % 48;
            float v;
            if (c < OD) {
                v = Rs[r * P16 + c];
                #pragma unroll
                for (int k = 0; k < SD; k++) v += HPs[r * P32 + k] * Hs[c * P32 + k];
            } else {
                v = HPs[r * P32 + (c - OD)];
            }
            aug[r * 49 + c] = v;
        }
        __syncthreads();

        // ---- Gauss-Jordan: single warp, register-resident, no barriers ----
        // lane l: row = l&15, half = l>>4 owns global cols [half*24, half*24+24)
        if (wid == 0) {
            const int row  = lane & 15;
            const int half = lane >> 4;
            const int cbase = half * 24;
            float rg[24];
            #pragma unroll
            for (int c = 0; c < 24; c++) rg[c] = aug[row * 49 + cbase + c];

            #pragma unroll
            for (int p = 0; p < OD; p++) {
                float piv = __shfl_sync(0xffffffffu, rg[p], p);    // aug[p][p] (lane p, half 0)
                float cv  = __shfl_sync(0xffffffffu, rg[p], row);  // aug[row][p]
                float rinv = 1.0f / piv;
                const int src = p + (half << 4);                   // lane holding row p, my half
                #pragma unroll
                for (int c = 0; c < 24; c++) {
                    float pr  = __shfl_sync(0xffffffffu, rg[c], src);
                    float prn = pr * rinv;
                    rg[c] = (row == p) ? prn : (rg[c] - cv * prn);
                }
            }
            // write K^T: global col g = cbase+c >= 16 -> K[i][o]=aug[o][16+i], i=g-16
            #pragma unroll
            for (int c = 0; c < 24; c++) {
                int g = cbase + c;
                if (g >= OD) KTs[row * P32 + (g - OD)] = rg[c];
            }
        }
        __syncthreads();

        // ---- W rows 0..31 (A^T): W[j][i] = F[i][j] - sum_o G[o][j] K[i][o] ----
        // thread: i = lane, j in {wid, wid+8, wid+16, wid+24}; K loads shared
        {
            const int i = lane, jg = wid;
            float w0 = FT[jg * P32 + i];
            float w1 = FT[(jg + 8) * P32 + i];
            float w2 = FT[(jg + 16) * P32 + i];
            float w3 = FT[(jg + 24) * P32 + i];
            #pragma unroll
            for (int o = 0; o < OD; o++) {
                float kv = KTs[o * P32 + i];           // lane stride-1
                w0 -= Gs[o * P32 + jg] * kv;           // broadcast
                w1 -= Gs[o * P32 + jg + 8] * kv;
                w2 -= Gs[o * P32 + jg + 16] * kv;
                w3 -= Gs[o * P32 + jg + 24] * kv;
            }
            float* wt = g_W[t];
            wt[jg * SD + i]        = w0;
            wt[(jg + 8) * SD + i]  = w1;
            wt[(jg + 16) * SD + i] = w2;
            wt[(jg + 24) * SD + i] = w3;
        }
        // ---- W rows 32..47 (K^T) ----
        #pragma unroll
        for (int s = 0; s < 2; s++) {
            int e = tid + s * 256;       // 512 = 16*32
            int o = e >> 5, i = e & 31;
            g_W[t][(SD + o) * SD + i] = KTs[o * P32 + i];
        }
        // ---- P_new = Pp - K @ HP : thread j = lane, i in {wid, wid+8, ...} ----
        {
            const int j = lane, ig = wid;
            float p0 = Pp[ig * P32 + j];
            float p1 = Pp[(ig + 8) * P32 + j];
            float p2 = Pp[(ig + 16) * P32 + j];
            float p3 = Pp[(ig + 24) * P32 + j];
            #pragma unroll
            for (int o = 0; o < OD; o++) {
                float hv = HPs[o * P32 + j];           // lane stride-1
                p0 -= KTs[o * P32 + ig] * hv;          // broadcast
                p1 -= KTs[o * P32 + ig + 8] * hv;
                p2 -= KTs[o * P32 + ig + 16] * hv;
                p3 -= KTs[o * P32 + ig + 24] * hv;
            }
            Ps[ig * P32 + j]        = p0;
            Ps[(ig + 8) * P32 + j]  = p1;
            Ps[(ig + 16) * P32 + j] = p2;
            Ps[(ig + 24) * P32 + j] = p3;
        }
        __syncthreads();
    }
}

// ---------------------------------------------------------------------------
// Phase 2: 8 warps/CTA, 2 batches per warp (shared W reads), 128 CTAs.
// W double-buffered with register prefetch; z prefetched into registers.
// ---------------------------------------------------------------------------
__global__ void __launch_bounds__(256, 1) phase2_kernel(
    const float* __restrict__ x0g,
    const float* __restrict__ meas,   // (B, T, 16)
    float* __restrict__ out)          // (B, T, 32)
{
    __shared__ float Wb[2][48 * SD];      // rows 0..31 = A^T, rows 32..47 = K^T
    __shared__ float xs[8][2][SD + 1];
    __shared__ float zs[8][2][OD];

    const int tid  = threadIdx.x;
    const int bl   = tid >> 5;
    const int lane = tid & 31;
    const int b0   = (blockIdx.x * 8 + bl) * 2;
    const int b1   = b0 + 1;
    const int lzb  = (lane < OD) ? b0 : b1;   // which batch this lane's z-prefetch serves
    const int lz   = lane & 15;

    // prologue: states, z_0, W_0
    xs[bl][0][lane] = x0g[b0 * SD + lane];
    xs[bl][1][lane] = x0g[b1 * SD + lane];
    zs[bl][lane >> 4][lz] = meas[(lzb * TT + 0) * OD + lz];
    {
        const float4* gw = (const float4*)g_W[0];
        float4* d = (float4*)Wb[0];
        d[tid] = gw[tid];
        if (tid < 128) d[256 + tid] = gw[256 + tid];
    }
    __syncthreads();

    #pragma unroll 1
    for (int t = 0; t < TT; t++) {
        // prefetch W_{t+1} and z_{t+1} into registers (latency overlapped w/ compute)
        float4 n0, n1;
        float zn;
        if (t + 1 < TT) {
            const float4* gw = (const float4*)g_W[t + 1];
            n0 = gw[tid];
            if (tid < 128) n1 = gw[256 + tid];
            zn = meas[(lzb * TT + (t + 1)) * OD + lz];
        }

        const float* AT = Wb[t & 1];
        const float* KT = Wb[t & 1] + SD * SD;
        float a0 = 0.f, a1 = 0.f, c0 = 0.f, c1 = 0.f;
        #pragma unroll
        for (int j = 0; j < SD; j += 2) {
            float w0 = AT[j * SD + lane];
            float w1 = AT[(j + 1) * SD + lane];
            a0 += w0 * xs[bl][0][j];
            c0 += w0 * xs[bl][1][j];
            a1 += w1 * xs[bl][0][j + 1];
            c1 += w1 * xs[bl][1][j + 1];
        }
        #pragma unroll
        for (int o = 0; o < OD; o += 2) {
            float w0 = KT[o * SD + lane];
            float w1 = KT[(o + 1) * SD + lane];
            a0 += w0 * zs[bl][0][o];
            c0 += w0 * zs[bl][1][o];
            a1 += w1 * zs[bl][0][o + 1];
            c1 += w1 * zs[bl][1][o + 1];
        }
        const float xa = a0 + a1;
        const float xc = c0 + c1;
        out[(b0 * TT + t) * SD + lane] = xa;
        out[(b1 * TT + t) * SD + lane] = xc;
        __syncthreads();   // reads of xs/zs/Wb[t&1] complete

        xs[bl][0][lane] = xa;
        xs[bl][1][lane] = xc;
        if (t + 1 < TT) {
            zs[bl][lane >> 4][lz] = zn;
            float4* d = (float4*)Wb[(t + 1) & 1];
            d[tid] = n0;
            if (tid < 128) d[256 + tid] = n1;
        }
        __syncthreads();   // new xs/zs/W visible
    }
}

// ---------------------------------------------------------------------------
extern "C" void kernel_launch(void* const* d_in, const int* in_sizes, int n_in,
                              void* d_out, int out_size) {
    const float* state0 = (const float*)d_in[0];  // (B, 32)
    const float* cov0   = (const float*)d_in[1];  // (B, 32, 32) identical per batch
    const float* meas   = (const float*)d_in[2];  // (B, 64, 16)
    const float* F      = (const float*)d_in[3];  // (32, 32)
    const float* H      = (const float*)d_in[4];  // (16, 32)
    const float* Q      = (const float*)d_in[5];  // (32, 32)
    const float* R      = (const float*)d_in[6];  // (16, 16)
    float* out = (float*)d_out;                   // (B, 64, 32)
    (void)in_sizes; (void)n_in; (void)out_size;

    phase1_kernel<<<1, 256>>>(F, H, Q, R, cov0);
    phase2_kernel<<<NB / 16, 256>>>(state0, meas, out);
}

// round 5
// speedup vs baseline: 1.1631x; 1.1631x over previous
#include <cuda_runtime.h>
#include <math.h>

// Kalman filter B=2048, T=64, STATE=32, OBS=16.
// Phase 1 (1 CTA): batch-independent Riccati recursion -> per-step W_t = [A_t^T ; K_t^T],
//                  with convergence early-exit (gain sequence converges; tail W_t constant).
// Phase 2 (128 CTAs): per-batch linear recursion x_t = A_t x_{t-1} + K_t z_t.

#define SD 32
#define OD 16
#define TT 64
#define NB 2048
#define P32 33
#define P16 17

// W_t layout: rows 0..31: W[j][i] = A_t[i][j]; rows 32..47: W[32+o][i] = K_t[i][o]
__device__ __align__(16) float g_W[TT][48 * SD];
__device__ int g_tconv;   // last step with a distinct W (W_t == W_tconv for t >= tconv)

// ---------------------------------------------------------------------------
// Phase 1
// ---------------------------------------------------------------------------
__global__ void __launch_bounds__(256, 1) phase1_kernel(
    const float* __restrict__ Fg,
    const float* __restrict__ Hg,
    const float* __restrict__ Qg,
    const float* __restrict__ Rg,
    const float* __restrict__ cov0)
{
    __shared__ float Fs[SD * P32];   // F row-major
    __shared__ float FT[SD * P32];   // F^T
    __shared__ float Qs[SD * P32];
    __shared__ float Hs[OD * P32];   // H row-major
    __shared__ float Rs[OD * P16];
    __shared__ float Gs[OD * P32];   // G = H@F : Gs[o][j]
    __shared__ float Ps[SD * P32];   // filtered covariance
    __shared__ float Pp[SD * P32];   // predicted covariance
    __shared__ float T1[SD * P32];   // temp (general-F path only)
    __shared__ float HPs[OD * P32];  // H @ Pp
    __shared__ float augA[OD * 49];  // ping-pong augmented [S | HP]
    __shared__ float augB[OD * 49];
    __shared__ float KPrev[OD * SD]; // previous K^T (for convergence test)
    __shared__ int fid;

    const int tid  = threadIdx.x;
    const int wid  = tid >> 5;
    const int lane = tid & 31;

    if (tid == 0) { fid = 1; g_tconv = TT - 1; }
    __syncthreads();

    {
        bool ok = true;
        #pragma unroll
        for (int s = 0; s < 4; s++) {
            int e = tid + s * 256;
            int i = e >> 5, j = e & 31;
            float f = Fg[e];
            Fs[i * P32 + j] = f;
            FT[j * P32 + i] = f;
            Qs[i * P32 + j] = Qg[e];
            Ps[i * P32 + j] = cov0[e];
            if (f != ((i == j) ? 1.0f : 0.0f)) ok = false;
        }
        if (!ok) fid = 0;
        #pragma unroll
        for (int s = 0; s < 2; s++) {
            int e = tid + s * 256;
            Hs[(e >> 5) * P32 + (e & 31)] = Hg[e];
        }
        Rs[(tid >> 4) * P16 + (tid & 15)] = Rg[tid];
    }
    __syncthreads();

    // G[o][j] = sum_k H[o][k] F[k][j]
    #pragma unroll
    for (int s = 0; s < 2; s++) {
        int e = tid + s * 256;
        int o = e >> 5, j = e & 31;
        float acc = 0.f;
        #pragma unroll
        for (int k = 0; k < SD; k++) acc += Hs[o * P32 + k] * FT[j * P32 + k];
        Gs[o * P32 + j] = acc;
    }
    const int ident = fid;
    __syncthreads();

    #pragma unroll 1
    for (int t = 0; t < TT; t++) {
        // ---- predict: Pp = F P F^T + Q ----
        if (ident) {
            #pragma unroll
            for (int s = 0; s < 4; s++) {
                int e = tid + s * 256;
                int idx = (e >> 5) * P32 + (e & 31);
                Pp[idx] = Ps[idx] + Qs[idx];
            }
        } else {
            #pragma unroll
            for (int s = 0; s < 4; s++) {
                int e = tid + s * 256;
                int i = e >> 5, j = e & 31;
                float acc = 0.f;
                #pragma unroll
                for (int k = 0; k < SD; k++) acc += Fs[i * P32 + k] * Ps[k * P32 + j];
                T1[i * P32 + j] = acc;
            }
            __syncthreads();
            #pragma unroll
            for (int s = 0; s < 4; s++) {
                int e = tid + s * 256;
                int i = e >> 5, j = e & 31;
                float acc = Qs[i * P32 + j];
                #pragma unroll
                for (int k = 0; k < SD; k++) acc += T1[i * P32 + k] * Fs[j * P32 + k];
                Pp[i * P32 + j] = acc;
            }
        }
        __syncthreads();

        // ---- HP[r][j] = sum_k H[r][k] Pp[k][j] ; rows r, r+8 share Pp loads ----
        {
            int r = wid, j = lane;
            float a0 = 0.f, a1 = 0.f;
            #pragma unroll
            for (int k = 0; k < SD; k++) {
                float pv = Pp[k * P32 + j];
                a0 += Hs[r * P32 + k] * pv;
                a1 += Hs[(r + 8) * P32 + k] * pv;
            }
            HPs[r * P32 + j] = a0;
            HPs[(r + 8) * P32 + j] = a1;
        }
        __syncthreads();

        // ---- augA = [S | HP], S = HP H^T + R  (FULL 768-element coverage) ----
        for (int e = tid; e < 768; e += 256) {
            int r = e / 48, c = e % 48;
            float v;
            if (c < OD) {
                v = Rs[r * P16 + c];
                #pragma unroll
                for (int k = 0; k < SD; k++) v += HPs[r * P32 + k] * Hs[c * P32 + k];
            } else {
                v = HPs[r * P32 + (c - OD)];
            }
            augA[r * 49 + c] = v;
        }
        __syncthreads();

        // ---- Gauss-Jordan: 2x2 block pivots, ping-pong, 1 barrier/round ----
        #pragma unroll 1
        for (int rd = 0; rd < 8; rd++) {
            const float* cu = (rd & 1) ? augB : augA;
            float* nx = (rd & 1) ? augA : augB;
            const int p = 2 * rd;
            const float a  = cu[p * 49 + p];
            const float bb = cu[p * 49 + p + 1];
            const float cc = cu[(p + 1) * 49 + p];
            const float dd = cu[(p + 1) * 49 + p + 1];
            const float rdet = 1.0f / (a * dd - bb * cc);
            const int aw = 46 - 2 * rd;
            const int cb = p + 2;
            const int tot = OD * aw;
            for (int e = tid; e < tot; e += 256) {
                int r = e / aw;
                int c = cb + (e - r * aw);
                float rp = cu[p * 49 + c];
                float rq = cu[(p + 1) * 49 + c];
                float np = (dd * rp - bb * rq) * rdet;
                float nq = (a * rq - cc * rp) * rdet;
                float val;
                if (r == p)          val = np;
                else if (r == p + 1) val = nq;
                else                 val = cu[r * 49 + c] - cu[r * 49 + p] * np - cu[r * 49 + p + 1] * nq;
                nx[r * 49 + c] = val;
            }
            __syncthreads();
        }
        // final result in augA: K[i][o] = augA[o*49 + 16 + i]

        // ---- stage A: store K^T rows of W + convergence diff ----
        bool okl = true;
        #pragma unroll
        for (int s = 0; s < 2; s++) {
            int e = tid + s * 256;       // 512 = 16*32
            int o = e >> 5, i = e & 31;
            float kv = augA[o * 49 + 16 + i];
            g_W[t][(SD + o) * SD + i] = kv;
            float pv = KPrev[e];
            KPrev[e] = kv;
            if (fabsf(kv - pv) >= 2e-7f) okl = false;
        }

        // ---- stage B: W rows 0..31 (A^T): W[j][i] = F[i][j] - sum_o G[o][j] K[i][o] ----
        {
            const int i = lane, jg = wid;
            float w0 = FT[jg * P32 + i];
            float w1 = FT[(jg + 8) * P32 + i];
            float w2 = FT[(jg + 16) * P32 + i];
            float w3 = FT[(jg + 24) * P32 + i];
            #pragma unroll
            for (int o = 0; o < OD; o++) {
                float kv = augA[o * 49 + 16 + i];
                w0 -= Gs[o * P32 + jg] * kv;
                w1 -= Gs[o * P32 + jg + 8] * kv;
                w2 -= Gs[o * P32 + jg + 16] * kv;
                w3 -= Gs[o * P32 + jg + 24] * kv;
            }
            float* wt = g_W[t];
            wt[jg * SD + i]        = w0;
            wt[(jg + 8) * SD + i]  = w1;
            wt[(jg + 16) * SD + i] = w2;
            wt[(jg + 24) * SD + i] = w3;
        }

        // ---- stage C: P_new = Pp - K @ HP ----
        {
            const int j = lane, ig = wid;
            float p0 = Pp[ig * P32 + j];
            float p1 = Pp[(ig + 8) * P32 + j];
            float p2 = Pp[(ig + 16) * P32 + j];
            float p3 = Pp[(ig + 24) * P32 + j];
            #pragma unroll
            for (int o = 0; o < OD; o++) {
                float hv = HPs[o * P32 + j];
                p0 -= augA[o * 49 + 16 + ig] * hv;
                p1 -= augA[o * 49 + 16 + ig + 8] * hv;
                p2 -= augA[o * 49 + 16 + ig + 16] * hv;
                p3 -= augA[o * 49 + 16 + ig + 24] * hv;
            }
            Ps[ig * P32 + j]        = p0;
            Ps[(ig + 8) * P32 + j]  = p1;
            Ps[(ig + 16) * P32 + j] = p2;
            Ps[(ig + 24) * P32 + j] = p3;
        }

        // ---- convergence check (doubles as end-of-step barrier) ----
        int conv = __syncthreads_and((int)(okl && (t > 0)));
        if (conv) {
            if (tid == 0) g_tconv = t;
            break;
        }
    }
}

// ---------------------------------------------------------------------------
// Phase 2: 8 warps/CTA, 2 batches per warp, 128 CTAs (single wave).
// W double-buffered with register prefetch; staging skipped after convergence.
// ---------------------------------------------------------------------------
__global__ void __launch_bounds__(256, 1) phase2_kernel(
    const float* __restrict__ x0g,
    const float* __restrict__ meas,   // (B, T, 16)
    float* __restrict__ out)          // (B, T, 32)
{
    __shared__ float Wb[2][48 * SD];
    __shared__ float xs[8][2][SD + 1];
    __shared__ float zs[8][2][OD];

    const int tid  = threadIdx.x;
    const int bl   = tid >> 5;
    const int lane = tid & 31;
    const int b0   = (blockIdx.x * 8 + bl) * 2;
    const int b1   = b0 + 1;
    const int lzb  = (lane < OD) ? b0 : b1;
    const int lz   = lane & 15;
    const int tconv = g_tconv;

    xs[bl][0][lane] = x0g[b0 * SD + lane];
    xs[bl][1][lane] = x0g[b1 * SD + lane];
    zs[bl][lane >> 4][lz] = meas[(lzb * TT + 0) * OD + lz];
    {
        const float4* gw = (const float4*)g_W[0];
        float4* d = (float4*)Wb[0];
        d[tid] = gw[tid];
        if (tid < 128) d[256 + tid] = gw[256 + tid];
    }
    __syncthreads();

    int cur = 0;       // buffer holding W for current t
    int tW = 0;        // which W index is loaded

    #pragma unroll 1
    for (int t = 0; t < TT; t++) {
        // next W index (clamped at convergence)
        int tn = (t + 1 < TT) ? ((t + 1 < tconv) ? (t + 1) : tconv) : tW;
        const bool stage = (tn != tW);

        float4 n0, n1;
        float zn;
        if (stage) {
            const float4* gw = (const float4*)g_W[tn];
            n0 = gw[tid];
            if (tid < 128) n1 = gw[256 + tid];
        }
        if (t + 1 < TT) zn = meas[(lzb * TT + (t + 1)) * OD + lz];

        const float* AT = Wb[cur];
        const float* KT = Wb[cur] + SD * SD;
        float a0 = 0.f, a1 = 0.f, c0 = 0.f, c1 = 0.f;
        #pragma unroll
        for (int j = 0; j < SD; j += 2) {
            float w0 = AT[j * SD + lane];
            float w1 = AT[(j + 1) * SD + lane];
            a0 += w0 * xs[bl][0][j];
            c0 += w0 * xs[bl][1][j];
            a1 += w1 * xs[bl][0][j + 1];
            c1 += w1 * xs[bl][1][j + 1];
        }
        #pragma unroll
        for (int o = 0; o < OD; o += 2) {
            float w0 = KT[o * SD + lane];
            float w1 = KT[(o + 1) * SD + lane];
            a0 += w0 * zs[bl][0][o];
            c0 += w0 * zs[bl][1][o];
            a1 += w1 * zs[bl][0][o + 1];
            c1 += w1 * zs[bl][1][o + 1];
        }
        const float xa = a0 + a1;
        const float xc = c0 + c1;
        out[(b0 * TT + t) * SD + lane] = xa;
        out[(b1 * TT + t) * SD + lane] = xc;
        __syncthreads();   // reads of xs/zs/Wb[cur] complete

        xs[bl][0][lane] = xa;
        xs[bl][1][lane] = xc;
        if (t + 1 < TT) zs[bl][lane >> 4][lz] = zn;
        if (stage) {
            float4* d = (float4*)Wb[cur ^ 1];
            d[tid] = n0;
            if (tid < 128) d[256 + tid] = n1;
            cur ^= 1;
            tW = tn;
        }
        __syncthreads();   // new xs/zs/W visible
    }
}

// ---------------------------------------------------------------------------
extern "C" void kernel_launch(void* const* d_in, const int* in_sizes, int n_in,
                              void* d_out, int out_size) {
    const float* state0 = (const float*)d_in[0];  // (B, 32)
    const float* cov0   = (const float*)d_in[1];  // (B, 32, 32) identical per batch
    const float* meas   = (const float*)d_in[2];  // (B, 64, 16)
    const float* F      = (const float*)d_in[3];  // (32, 32)
    const float* H      = (const float*)d_in[4];  // (16, 32)
    const float* Q      = (const float*)d_in[5];  // (32, 32)
    const float* R      = (const float*)d_in[6];  // (16, 16)
    float* out = (float*)d_out;                   // (B, 64, 32)
    (void)in_sizes; (void)n_in; (void)out_size;

    phase1_kernel<<<1, 256>>>(F, H, Q, R, cov0);
    phase2_kernel<<<NB / 16, 256>>>(state0, meas, out);
}

// round 6
// speedup vs baseline: 1.3154x; 1.1310x over previous
#include <cuda_runtime.h>
#include <math.h>

// Kalman filter B=2048, T=64, STATE=32, OBS=16.
// Phase 1 (1 CTA): batch-independent Riccati recursion -> per-step W_t = [A_t^T ; K_t^T],
//                  with convergence early-exit. LDS-minimized via step-invariant
//                  operands (H rows, G rows) cached in registers.
// Phase 2 (128 CTAs): per-batch linear recursion x_t = A_t x_{t-1} + K_t z_t.

#define SD 32
#define OD 16
#define TT 64
#define NB 2048
#define P32 33
#define P16 17

// W_t layout: rows 0..31: W[j][i] = A_t[i][j]; rows 32..47: W[32+o][i] = K_t[i][o]
__device__ __align__(16) float g_W[TT][48 * SD];
__device__ int g_tconv;   // last step with a distinct W (W_t == W_tconv for t >= tconv)

// ---------------------------------------------------------------------------
// Phase 1
// ---------------------------------------------------------------------------
__global__ void __launch_bounds__(256, 1) phase1_kernel(
    const float* __restrict__ Fg,
    const float* __restrict__ Hg,
    const float* __restrict__ Qg,
    const float* __restrict__ Rg,
    const float* __restrict__ cov0)
{
    __shared__ float Fs[SD * P32];   // F row-major
    __shared__ float FT[SD * P32];   // F^T
    __shared__ float Qs[SD * P32];
    __shared__ float Hs[OD * P32];   // H row-major
    __shared__ float Rs[OD * P16];
    __shared__ float Gs[OD * P32];   // G = H@F : Gs[o][j]
    __shared__ float Ps[SD * P32];   // filtered covariance
    __shared__ float Pp[SD * P32];   // predicted covariance
    __shared__ float T1[SD * P32];   // temp (general-F path only)
    __shared__ float HPs[OD * P32];  // H @ Pp
    __shared__ float augA[OD * 49];  // ping-pong augmented [S | HP]
    __shared__ float augB[OD * 49];
    __shared__ float KPrev[OD * SD]; // previous K^T (for convergence test)
    __shared__ int fid;

    const int tid  = threadIdx.x;
    const int wid  = tid >> 5;
    const int lane = tid & 31;
    const int half = lane >> 4;
    const int rsel = wid + 8 * half;   // this thread's H/G row for HP & S stages

    if (tid == 0) { fid = 1; g_tconv = TT - 1; }
    __syncthreads();

    {
        bool ok = true;
        #pragma unroll
        for (int s = 0; s < 4; s++) {
            int e = tid + s * 256;
            int i = e >> 5, j = e & 31;
            float f = Fg[e];
            Fs[i * P32 + j] = f;
            FT[j * P32 + i] = f;
            Qs[i * P32 + j] = Qg[e];
            Ps[i * P32 + j] = cov0[e];
            if (f != ((i == j) ? 1.0f : 0.0f)) ok = false;
        }
        if (!ok) fid = 0;
        #pragma unroll
        for (int s = 0; s < 2; s++) {
            int e = tid + s * 256;
            Hs[(e >> 5) * P32 + (e & 31)] = Hg[e];
        }
        Rs[(tid >> 4) * P16 + (tid & 15)] = Rg[tid];
    }
    __syncthreads();

    // step-invariant register cache: this thread's H row
    float hsel[SD];
    #pragma unroll
    for (int k = 0; k < SD; k++) hsel[k] = Hs[rsel * P32 + k];

    // G[o][j] = sum_k H[o][k] F[k][j]
    #pragma unroll
    for (int s = 0; s < 2; s++) {
        int e = tid + s * 256;
        int o = e >> 5, j = e & 31;
        float acc = 0.f;
        #pragma unroll
        for (int k = 0; k < SD; k++) acc += Hs[o * P32 + k] * FT[j * P32 + k];
        Gs[o * P32 + j] = acc;
    }
    const int ident = fid;
    __syncthreads();

    // step-invariant register cache: G columns used by stage B (j = wid + 8*m)
    float Greg[OD * 4];
    #pragma unroll
    for (int o = 0; o < OD; o++) {
        Greg[o * 4 + 0] = Gs[o * P32 + wid];
        Greg[o * 4 + 1] = Gs[o * P32 + wid + 8];
        Greg[o * 4 + 2] = Gs[o * P32 + wid + 16];
        Greg[o * 4 + 3] = Gs[o * P32 + wid + 24];
    }

    #pragma unroll 1
    for (int t = 0; t < TT; t++) {
        // ---- predict: Pp = F P F^T + Q ----
        if (ident) {
            #pragma unroll
            for (int s = 0; s < 4; s++) {
                int e = tid + s * 256;
                int idx = (e >> 5) * P32 + (e & 31);
                Pp[idx] = Ps[idx] + Qs[idx];
            }
        } else {
            #pragma unroll
            for (int s = 0; s < 4; s++) {
                int e = tid + s * 256;
                int i = e >> 5, j = e & 31;
                float acc = 0.f;
                #pragma unroll
                for (int k = 0; k < SD; k++) acc += Fs[i * P32 + k] * Ps[k * P32 + j];
                T1[i * P32 + j] = acc;
            }
            __syncthreads();
            #pragma unroll
            for (int s = 0; s < 4; s++) {
                int e = tid + s * 256;
                int i = e >> 5, j = e & 31;
                float acc = Qs[i * P32 + j];
                #pragma unroll
                for (int k = 0; k < SD; k++) acc += T1[i * P32 + k] * Fs[j * P32 + k];
                Pp[i * P32 + j] = acc;
            }
        }
        __syncthreads();

        // ---- HP[rsel][j0], HP[rsel][j0+16] = sum_k H[rsel][k] Pp[k][j] (H in regs) ----
        {
            const int j0 = lane & 15;
            float a0 = 0.f, a1 = 0.f;
            #pragma unroll
            for (int k = 0; k < SD; k++) {
                float p0 = Pp[k * P32 + j0];
                float p1 = Pp[k * P32 + j0 + 16];
                a0 += hsel[k] * p0;
                a1 += hsel[k] * p1;
            }
            HPs[rsel * P32 + j0]      = a0;
            HPs[rsel * P32 + j0 + 16] = a1;
        }
        __syncthreads();

        // ---- S[r][c] = R + sum_k HP[r][k] H[c][k]  (c = rsel, H in regs) ----
        {
            const int r = lane & 15;
            float acc = Rs[r * P16 + rsel];
            #pragma unroll
            for (int k = 0; k < SD; k++) acc += HPs[r * P32 + k] * hsel[k];
            augA[r * 49 + rsel] = acc;
        }
        // ---- aug columns 16..47 = HP ----
        #pragma unroll
        for (int s = 0; s < 2; s++) {
            int e = tid + s * 256;
            int r = e >> 5, i = e & 31;
            augA[r * 49 + 16 + i] = HPs[r * P32 + i];
        }
        __syncthreads();

        // ---- Gauss-Jordan: 2x2 block pivots, ping-pong, 1 barrier/round ----
        #pragma unroll 1
        for (int rd = 0; rd < 8; rd++) {
            const float* cu = (rd & 1) ? augB : augA;
            float* nx = (rd & 1) ? augA : augB;
            const int p = 2 * rd;
            const float a  = cu[p * 49 + p];
            const float bb = cu[p * 49 + p + 1];
            const float cc = cu[(p + 1) * 49 + p];
            const float dd = cu[(p + 1) * 49 + p + 1];
            const float rdet = 1.0f / (a * dd - bb * cc);
            const int aw = 46 - 2 * rd;
            const int cb = p + 2;
            const int tot = OD * aw;
            for (int e = tid; e < tot; e += 256) {
                int r = e / aw;
                int c = cb + (e - r * aw);
                float rp = cu[p * 49 + c];
                float rq = cu[(p + 1) * 49 + c];
                float np = (dd * rp - bb * rq) * rdet;
                float nq = (a * rq - cc * rp) * rdet;
                float val;
                if (r == p)          val = np;
                else if (r == p + 1) val = nq;
                else                 val = cu[r * 49 + c] - cu[r * 49 + p] * np - cu[r * 49 + p + 1] * nq;
                nx[r * 49 + c] = val;
            }
            __syncthreads();
        }
        // final result in augA: K[i][o] = augA[o*49 + 16 + i]

        // ---- stage A: store K^T rows of W + convergence diff ----
        bool okl = true;
        #pragma unroll
        for (int s = 0; s < 2; s++) {
            int e = tid + s * 256;       // 512 = 16*32
            int o = e >> 5, i = e & 31;
            float kv = augA[o * 49 + 16 + i];
            g_W[t][(SD + o) * SD + i] = kv;
            float pv = KPrev[e];
            KPrev[e] = kv;
            if (fabsf(kv - pv) >= 3e-6f) okl = false;
        }

        // ---- stage B: W rows 0..31 (A^T): W[j][i] = F[i][j] - sum_o G[o][j] K[i][o] ----
        {
            const int i = lane, jg = wid;
            float w0 = FT[jg * P32 + i];
            float w1 = FT[(jg + 8) * P32 + i];
            float w2 = FT[(jg + 16) * P32 + i];
            float w3 = FT[(jg + 24) * P32 + i];
            #pragma unroll
            for (int o = 0; o < OD; o++) {
                float kv = augA[o * 49 + 16 + i];
                w0 -= Greg[o * 4 + 0] * kv;
                w1 -= Greg[o * 4 + 1] * kv;
                w2 -= Greg[o * 4 + 2] * kv;
                w3 -= Greg[o * 4 + 3] * kv;
            }
            float* wt = g_W[t];
            wt[jg * SD + i]        = w0;
            wt[(jg + 8) * SD + i]  = w1;
            wt[(jg + 16) * SD + i] = w2;
            wt[(jg + 24) * SD + i] = w3;
        }

        // ---- stage C: P_new = Pp - K @ HP ----
        {
            const int j = lane, ig = wid;
            float p0 = Pp[ig * P32 + j];
            float p1 = Pp[(ig + 8) * P32 + j];
            float p2 = Pp[(ig + 16) * P32 + j];
            float p3 = Pp[(ig + 24) * P32 + j];
            #pragma unroll
            for (int o = 0; o < OD; o++) {
                float hv = HPs[o * P32 + j];
                p0 -= augA[o * 49 + 16 + ig] * hv;
                p1 -= augA[o * 49 + 16 + ig + 8] * hv;
                p2 -= augA[o * 49 + 16 + ig + 16] * hv;
                p3 -= augA[o * 49 + 16 + ig + 24] * hv;
            }
            Ps[ig * P32 + j]        = p0;
            Ps[(ig + 8) * P32 + j]  = p1;
            Ps[(ig + 16) * P32 + j] = p2;
            Ps[(ig + 24) * P32 + j] = p3;
        }

        // ---- convergence check (doubles as end-of-step barrier) ----
        int conv = __syncthreads_and((int)(okl && (t > 0)));
        if (conv) {
            if (tid == 0) g_tconv = t;
            break;
        }
    }
}

// ---------------------------------------------------------------------------
// Phase 2: 8 warps/CTA, 2 batches per warp, 128 CTAs (single wave).
// W double-buffered with register prefetch; staging skipped after convergence.
// ---------------------------------------------------------------------------
__global__ void __launch_bounds__(256, 1) phase2_kernel(
    const float* __restrict__ x0g,
    const float* __restrict__ meas,   // (B, T, 16)
    float* __restrict__ out)          // (B, T, 32)
{
    __shared__ float Wb[2][48 * SD];
    __shared__ float xs[8][2][SD + 1];
    __shared__ float zs[8][2][OD];

    const int tid  = threadIdx.x;
    const int bl   = tid >> 5;
    const int lane = tid & 31;
    const int b0   = (blockIdx.x * 8 + bl) * 2;
    const int b1   = b0 + 1;
    const int lzb  = (lane < OD) ? b0 : b1;
    const int lz   = lane & 15;
    const int tconv = g_tconv;

    xs[bl][0][lane] = x0g[b0 * SD + lane];
    xs[bl][1][lane] = x0g[b1 * SD + lane];
    zs[bl][lane >> 4][lz] = meas[(lzb * TT + 0) * OD + lz];
    {
        const float4* gw = (const float4*)g_W[0];
        float4* d = (float4*)Wb[0];
        d[tid] = gw[tid];
        if (tid < 128) d[256 + tid] = gw[256 + tid];
    }
    __syncthreads();

    int cur = 0;       // buffer holding W for current t
    int tW = 0;        // which W index is loaded

    #pragma unroll 1
    for (int t = 0; t < TT; t++) {
        int tn = (t + 1 < TT) ? ((t + 1 < tconv) ? (t + 1) : tconv) : tW;
        const bool stage = (tn != tW);

        float4 n0, n1;
        float zn;
        if (stage) {
            const float4* gw = (const float4*)g_W[tn];
            n0 = gw[tid];
            if (tid < 128) n1 = gw[256 + tid];
        }
        if (t + 1 < TT) zn = meas[(lzb * TT + (t + 1)) * OD + lz];

        const float* AT = Wb[cur];
        const float* KT = Wb[cur] + SD * SD;
        float a0 = 0.f, a1 = 0.f, c0 = 0.f, c1 = 0.f;
        #pragma unroll
        for (int j = 0; j < SD; j += 2) {
            float w0 = AT[j * SD + lane];
            float w1 = AT[(j + 1) * SD + lane];
            a0 += w0 * xs[bl][0][j];
            c0 += w0 * xs[bl][1][j];
            a1 += w1 * xs[bl][0][j + 1];
            c1 += w1 * xs[bl][1][j + 1];
        }
        #pragma unroll
        for (int o = 0; o < OD; o += 2) {
            float w0 = KT[o * SD + lane];
            float w1 = KT[(o + 1) * SD + lane];
            a0 += w0 * zs[bl][0][o];
            c0 += w0 * zs[bl][1][o];
            a1 += w1 * zs[bl][0][o + 1];
            c1 += w1 * zs[bl][1][o + 1];
        }
        const float xa = a0 + a1;
        const float xc = c0 + c1;
        out[(b0 * TT + t) * SD + lane] = xa;
        out[(b1 * TT + t) * SD + lane] = xc;
        __syncthreads();   // reads of xs/zs/Wb[cur] complete

        xs[bl][0][lane] = xa;
        xs[bl][1][lane] = xc;
        if (t + 1 < TT) zs[bl][lane >> 4][lz] = zn;
        if (stage) {
            float4* d = (float4*)Wb[cur ^ 1];
            d[tid] = n0;
            if (tid < 128) d[256 + tid] = n1;
            cur ^= 1;
            tW = tn;
        }
        __syncthreads();   // new xs/zs/W visible
    }
}

// ---------------------------------------------------------------------------
extern "C" void kernel_launch(void* const* d_in, const int* in_sizes, int n_in,
                              void* d_out, int out_size) {
    const float* state0 = (const float*)d_in[0];  // (B, 32)
    const float* cov0   = (const float*)d_in[1];  // (B, 32, 32) identical per batch
    const float* meas   = (const float*)d_in[2];  // (B, 64, 16)
    const float* F      = (const float*)d_in[3];  // (32, 32)
    const float* H      = (const float*)d_in[4];  // (16, 32)
    const float* Q      = (const float*)d_in[5];  // (32, 32)
    const float* R      = (const float*)d_in[6];  // (16, 16)
    float* out = (float*)d_out;                   // (B, 64, 32)
    (void)in_sizes; (void)n_in; (void)out_size;

    phase1_kernel<<<1, 256>>>(F, H, Q, R, cov0);
    phase2_kernel<<<NB / 16, 256>>>(state0, meas, out);
}

// round 7
// speedup vs baseline: 4.2116x; 3.2017x over previous
#include <cuda_runtime.h>
#include <math.h>

// Kalman filter B=2048, T=64, STATE=32, OBS=16.
// SPECIAL PATH (F=I, Q=qI, R=rI, cov0=I — verified on device):
//   Riccati diagonalizes in SVD basis of H. prep_kernel: one-sided Jacobi SVD of H
//   + scalar gain recursions. phase2_new: per-batch 16 scalar scans + two matvecs.
// FALLBACK: previous verified phase1/phase2 (guarded by g_special).

#define SD 32
#define OD 16
#define TT 64
#define NB 2048
#define P32 33
#define P16 17

__device__ int g_special;
__device__ float g_U16[OD * OD];   // w_i = sum_m g_U16[i*16+m] * z_m   (U^T z)
__device__ float g_V[SD * OD];     // g_V[j*16+i] = V[j][i]
__device__ float g_ab[TT * 32];    // [t][i]=a_i,t  [t][16+i]=k_i,t

// fallback tables
__device__ __align__(16) float g_W[TT][48 * SD];
__device__ int g_tconv;

// ---------------------------------------------------------------------------
// prep: specialness check + Jacobi SVD + scalar gain recursion
// ---------------------------------------------------------------------------
__global__ void __launch_bounds__(256, 1) prep_kernel(
    const float* __restrict__ Fg, const float* __restrict__ Hg,
    const float* __restrict__ Qg, const float* __restrict__ Rg,
    const float* __restrict__ cov0)
{
    __shared__ float Hw[OD * 33];     // working copy of H (rows get rotated)
    __shared__ float Wacc[OD * 17];   // accumulated rotations (R so that R H = Sigma V^T)
    __shared__ float sig[OD];
    __shared__ float qr[2];

    const int tid = threadIdx.x;
    const float q = Qg[0], r = Rg[0];
    if (tid == 0) { qr[0] = q; qr[1] = r; }

    bool ok = (r > 0.f) && (q >= 0.f);
    #pragma unroll
    for (int s = 0; s < 4; s++) {
        int e = tid + s * 256;
        int i = e >> 5, j = e & 31;
        float ide = (i == j) ? 1.f : 0.f;
        if (Fg[e] != ide) ok = false;
        if (cov0[e] != ide) ok = false;
        if (Qg[e] != ((i == j) ? q : 0.f)) ok = false;
    }
    {
        int i = tid >> 4, j = tid & 15;
        if (Rg[tid] != ((i == j) ? r : 0.f)) ok = false;
    }
    int special = __syncthreads_and((int)ok);
    if (tid == 0) g_special = special;
    if (!special) return;

    // init Hw = H, Wacc = I
    #pragma unroll
    for (int s = 0; s < 2; s++) {
        int e = tid + s * 256;
        Hw[(e >> 5) * 33 + (e & 31)] = Hg[e];
    }
    { int i = tid >> 4, m = tid & 15; Wacc[i * 17 + m] = (i == m) ? 1.f : 0.f; }
    __syncthreads();

    const int w = tid >> 5, lane = tid & 31;

    // one-sided Jacobi: orthogonalize the 16 rows of Hw. 8 disjoint pairs/round.
    for (int sweep = 0; sweep < 8; sweep++) {
        for (int rr = 0; rr < 15; rr++) {
            int p, qq;
            if (w == 0) { p = 0; qq = 1 + rr; }
            else { p = 1 + ((rr + w) % 15); qq = 1 + ((rr + 15 - w) % 15); }
            float hp = Hw[p * 33 + lane];
            float hq = Hw[qq * 33 + lane];
            float al = hp * hp, be = hq * hq, ga = hp * hq;
            #pragma unroll
            for (int off = 16; off; off >>= 1) {
                al += __shfl_xor_sync(0xffffffffu, al, off);
                be += __shfl_xor_sync(0xffffffffu, be, off);
                ga += __shfl_xor_sync(0xffffffffu, ga, off);
            }
            if (ga * ga > 1e-16f * al * be) {
                float tau = (be - al) / (2.f * ga);
                float tt = ((tau >= 0.f) ? 1.f : -1.f) / (fabsf(tau) + sqrtf(1.f + tau * tau));
                float c = rsqrtf(1.f + tt * tt);
                float s = c * tt;
                Hw[p * 33 + lane]  = c * hp - s * hq;
                Hw[qq * 33 + lane] = s * hp + c * hq;
                if (lane < OD) {
                    float up = Wacc[p * 17 + lane], uq = Wacc[qq * 17 + lane];
                    Wacc[p * 17 + lane]  = c * up - s * uq;
                    Wacc[qq * 17 + lane] = s * up + c * uq;
                }
            }
            __syncthreads();
        }
    }

    // row norms -> sigma
    {
        int row0 = w * 2;
        #pragma unroll
        for (int rep = 0; rep < 2; rep++) {
            int row = row0 + rep;
            float v = Hw[row * 33 + lane];
            float ss = v * v;
            #pragma unroll
            for (int off = 16; off; off >>= 1) ss += __shfl_xor_sync(0xffffffffu, ss, off);
            if (lane == 0) sig[row] = sqrtf(ss);
        }
    }
    __syncthreads();

    // V[j][i] = Hw[i][j]/sigma_i ; U^T rows = Wacc rows
    #pragma unroll
    for (int s = 0; s < 2; s++) {
        int e = tid + s * 256;       // 512
        int j = e >> 4, i = e & 15;
        float sg = sig[i];
        float rsg = (sg > 1e-20f) ? (1.f / sg) : 0.f;
        g_V[j * 16 + i] = Hw[i * 33 + j] * rsg;
    }
    { int i = tid >> 4, m = tid & 15; g_U16[i * 16 + m] = Wacc[i * 17 + m]; }

    // scalar gain recursion per component
    if (tid < OD) {
        float sg = sig[tid];
        float lam = sg * sg;
        float p = 1.f;
        const float qv = qr[0], rv = qr[1];
        for (int t = 0; t < TT; t++) {
            float pp = p + qv;
            float dinv = 1.f / (lam * pp + rv);
            float a = rv * dinv;
            float kk = pp * sg * dinv;
            g_ab[t * 32 + tid] = a;
            g_ab[t * 32 + 16 + tid] = kk;
            p = a * pp;
        }
    }
}

// ---------------------------------------------------------------------------
// phase2 special: per batch, w = U^T z; scalar scans y_t = a y + k w; x = u + V y
// ---------------------------------------------------------------------------
__global__ void __launch_bounds__(128, 1) phase2_new_kernel(
    const float* __restrict__ x0g,
    const float* __restrict__ meas,   // (B, T, 16)
    float* __restrict__ out)          // (B, T, 32)
{
    if (!g_special) return;

    __shared__ float zb[4][TT * OD];  // per-warp buffer: z -> w -> y
    __shared__ float ab[TT * 32];
    __shared__ float Us[OD * OD];
    __shared__ float Vs[SD * 17];

    const int tid  = threadIdx.x;
    const int w    = tid >> 5;
    const int lane = tid & 31;
    const int i16  = lane & 15;

    for (int e = tid; e < TT * 32; e += 128) ab[e] = g_ab[e];
    for (int e = tid; e < OD * OD; e += 128) Us[e] = g_U16[e];
    for (int e = tid; e < SD * OD; e += 128) Vs[(e >> 4) * 17 + (e & 15)] = g_V[e];
    __syncthreads();

    float Ureg[16], Vreg[16];
    #pragma unroll
    for (int m = 0; m < 16; m++) Ureg[m] = Us[i16 * 16 + m];
    #pragma unroll
    for (int m = 0; m < 16; m++) Vreg[m] = Vs[lane * 17 + m];
    float* zw = zb[w];

    #pragma unroll 1
    for (int sub = 0; sub < 2; sub++) {
        const int b = (blockIdx.x * 4 + w) * 2 + sub;

        // load z tile (1024 floats, coalesced)
        const float4* zg = (const float4*)(meas + (size_t)b * TT * OD);
        float4* z4 = (float4*)zw;
        #pragma unroll
        for (int it = 0; it < 8; it++) z4[it * 32 + lane] = zg[it * 32 + lane];
        float x0reg = x0g[b * SD + lane];
        __syncwarp();

        // w[t] = U^T z[t], in place (2 t per iteration; reads complete before writes)
        #pragma unroll 4
        for (int it = 0; it < 32; it++) {
            int t = it * 2 + (lane >> 4);
            float acc = 0.f;
            #pragma unroll
            for (int m = 0; m < 16; m++) acc += Ureg[m] * zw[t * 16 + m];
            __syncwarp();
            zw[t * 16 + i16] = acc;
            __syncwarp();
        }

        // y0 = V^T x0 (component i16, identical in both half-warps)
        float y = 0.f;
        #pragma unroll
        for (int j = 0; j < 32; j++)
            y += Vs[j * 17 + i16] * __shfl_sync(0xffffffffu, x0reg, j);

        // u[j] = x0[j] - sum_i V[j][i] y0_i
        float u = x0reg;
        #pragma unroll
        for (int m = 0; m < 16; m++)
            u -= Vreg[m] * __shfl_sync(0xffffffffu, y, m);

        // scalar scans (lanes 0..15 only; overwrite w with y in place)
        if (lane < 16) {
            #pragma unroll 1
            for (int t = 0; t < TT; t++) {
                float wv = zw[t * 16 + i16];
                y = ab[t * 32 + i16] * y + ab[t * 32 + 16 + i16] * wv;
                zw[t * 16 + i16] = y;
            }
        }
        __syncwarp();

        // out[t][j] = u[j] + sum_i V[j][i] y[t][i]
        float* ob = out + (size_t)b * TT * SD;
        #pragma unroll 2
        for (int t = 0; t < TT; t++) {
            float acc = u;
            #pragma unroll
            for (int m = 0; m < 16; m++) acc += Vreg[m] * zw[t * 16 + m];
            ob[t * SD + lane] = acc;
        }
        __syncwarp();
    }
}

// ---------------------------------------------------------------------------
// FALLBACK phase 1 (verified R6 path)
// ---------------------------------------------------------------------------
__global__ void __launch_bounds__(256, 1) phase1_kernel(
    const float* __restrict__ Fg, const float* __restrict__ Hg,
    const float* __restrict__ Qg, const float* __restrict__ Rg,
    const float* __restrict__ cov0)
{
    if (g_special) return;

    __shared__ float Fs[SD * P32];
    __shared__ float FT[SD * P32];
    __shared__ float Qs[SD * P32];
    __shared__ float Hs[OD * P32];
    __shared__ float Rs[OD * P16];
    __shared__ float Gs[OD * P32];
    __shared__ float Ps[SD * P32];
    __shared__ float Pp[SD * P32];
    __shared__ float T1[SD * P32];
    __shared__ float HPs[OD * P32];
    __shared__ float augA[OD * 49];
    __shared__ float augB[OD * 49];
    __shared__ float KPrev[OD * SD];
    __shared__ int fid;

    const int tid  = threadIdx.x;
    const int wid  = tid >> 5;
    const int lane = tid & 31;
    const int half = lane >> 4;
    const int rsel = wid + 8 * half;

    if (tid == 0) { fid = 1; g_tconv = TT - 1; }
    __syncthreads();

    {
        bool ok = true;
        #pragma unroll
        for (int s = 0; s < 4; s++) {
            int e = tid + s * 256;
            int i = e >> 5, j = e & 31;
            float f = Fg[e];
            Fs[i * P32 + j] = f;
            FT[j * P32 + i] = f;
            Qs[i * P32 + j] = Qg[e];
            Ps[i * P32 + j] = cov0[e];
            if (f != ((i == j) ? 1.0f : 0.0f)) ok = false;
        }
        if (!ok) fid = 0;
        #pragma unroll
        for (int s = 0; s < 2; s++) {
            int e = tid + s * 256;
            Hs[(e >> 5) * P32 + (e & 31)] = Hg[e];
        }
        Rs[(tid >> 4) * P16 + (tid & 15)] = Rg[tid];
    }
    __syncthreads();

    float hsel[SD];
    #pragma unroll
    for (int k = 0; k < SD; k++) hsel[k] = Hs[rsel * P32 + k];

    #pragma unroll
    for (int s = 0; s < 2; s++) {
        int e = tid + s * 256;
        int o = e >> 5, j = e & 31;
        float acc = 0.f;
        #pragma unroll
        for (int k = 0; k < SD; k++) acc += Hs[o * P32 + k] * FT[j * P32 + k];
        Gs[o * P32 + j] = acc;
    }
    const int ident = fid;
    __syncthreads();

    float Greg[OD * 4];
    #pragma unroll
    for (int o = 0; o < OD; o++) {
        Greg[o * 4 + 0] = Gs[o * P32 + wid];
        Greg[o * 4 + 1] = Gs[o * P32 + wid + 8];
        Greg[o * 4 + 2] = Gs[o * P32 + wid + 16];
        Greg[o * 4 + 3] = Gs[o * P32 + wid + 24];
    }

    #pragma unroll 1
    for (int t = 0; t < TT; t++) {
        if (ident) {
            #pragma unroll
            for (int s = 0; s < 4; s++) {
                int e = tid + s * 256;
                int idx = (e >> 5) * P32 + (e & 31);
                Pp[idx] = Ps[idx] + Qs[idx];
            }
        } else {
            #pragma unroll
            for (int s = 0; s < 4; s++) {
                int e = tid + s * 256;
                int i = e >> 5, j = e & 31;
                float acc = 0.f;
                #pragma unroll
                for (int k = 0; k < SD; k++) acc += Fs[i * P32 + k] * Ps[k * P32 + j];
                T1[i * P32 + j] = acc;
            }
            __syncthreads();
            #pragma unroll
            for (int s = 0; s < 4; s++) {
                int e = tid + s * 256;
                int i = e >> 5, j = e & 31;
                float acc = Qs[i * P32 + j];
                #pragma unroll
                for (int k = 0; k < SD; k++) acc += T1[i * P32 + k] * Fs[j * P32 + k];
                Pp[i * P32 + j] = acc;
            }
        }
        __syncthreads();

        {
            const int j0 = lane & 15;
            float a0 = 0.f, a1 = 0.f;
            #pragma unroll
            for (int k = 0; k < SD; k++) {
                float p0 = Pp[k * P32 + j0];
                float p1 = Pp[k * P32 + j0 + 16];
                a0 += hsel[k] * p0;
                a1 += hsel[k] * p1;
            }
            HPs[rsel * P32 + j0]      = a0;
            HPs[rsel * P32 + j0 + 16] = a1;
        }
        __syncthreads();

        {
            const int rr = lane & 15;
            float acc = Rs[rr * P16 + rsel];
            #pragma unroll
            for (int k = 0; k < SD; k++) acc += HPs[rr * P32 + k] * hsel[k];
            augA[rr * 49 + rsel] = acc;
        }
        #pragma unroll
        for (int s = 0; s < 2; s++) {
            int e = tid + s * 256;
            int rr = e >> 5, i = e & 31;
            augA[rr * 49 + 16 + i] = HPs[rr * P32 + i];
        }
        __syncthreads();

        #pragma unroll 1
        for (int rd = 0; rd < 8; rd++) {
            const float* cu = (rd & 1) ? augB : augA;
            float* nx = (rd & 1) ? augA : augB;
            const int p = 2 * rd;
            const float a  = cu[p * 49 + p];
            const float bb = cu[p * 49 + p + 1];
            const float cc = cu[(p + 1) * 49 + p];
            const float dd = cu[(p + 1) * 49 + p + 1];
            const float rdet = 1.0f / (a * dd - bb * cc);
            const int aw = 46 - 2 * rd;
            const int cb = p + 2;
            const int tot = OD * aw;
            for (int e = tid; e < tot; e += 256) {
                int rr = e / aw;
                int c = cb + (e - rr * aw);
                float rp = cu[p * 49 + c];
                float rq = cu[(p + 1) * 49 + c];
                float np = (dd * rp - bb * rq) * rdet;
                float nq = (a * rq - cc * rp) * rdet;
                float val;
                if (rr == p)          val = np;
                else if (rr == p + 1) val = nq;
                else                  val = cu[rr * 49 + c] - cu[rr * 49 + p] * np - cu[rr * 49 + p + 1] * nq;
                nx[rr * 49 + c] = val;
            }
            __syncthreads();
        }

        bool okl = true;
        #pragma unroll
        for (int s = 0; s < 2; s++) {
            int e = tid + s * 256;
            int o = e >> 5, i = e & 31;
            float kv = augA[o * 49 + 16 + i];
            g_W[t][(SD + o) * SD + i] = kv;
            float pv = KPrev[e];
            KPrev[e] = kv;
            if (fabsf(kv - pv) >= 3e-6f) okl = false;
        }

        {
            const int i = lane, jg = wid;
            float w0 = FT[jg * P32 + i];
            float w1 = FT[(jg + 8) * P32 + i];
            float w2 = FT[(jg + 16) * P32 + i];
            float w3 = FT[(jg + 24) * P32 + i];
            #pragma unroll
            for (int o = 0; o < OD; o++) {
                float kv = augA[o * 49 + 16 + i];
                w0 -= Greg[o * 4 + 0] * kv;
                w1 -= Greg[o * 4 + 1] * kv;
                w2 -= Greg[o * 4 + 2] * kv;
                w3 -= Greg[o * 4 + 3] * kv;
            }
            float* wt = g_W[t];
            wt[jg * SD + i]        = w0;
            wt[(jg + 8) * SD + i]  = w1;
            wt[(jg + 16) * SD + i] = w2;
            wt[(jg + 24) * SD + i] = w3;
        }

        {
            const int j = lane, ig = wid;
            float p0 = Pp[ig * P32 + j];
            float p1 = Pp[(ig + 8) * P32 + j];
            float p2 = Pp[(ig + 16) * P32 + j];
            float p3 = Pp[(ig + 24) * P32 + j];
            #pragma unroll
            for (int o = 0; o < OD; o++) {
                float hv = HPs[o * P32 + j];
                p0 -= augA[o * 49 + 16 + ig] * hv;
                p1 -= augA[o * 49 + 16 + ig + 8] * hv;
                p2 -= augA[o * 49 + 16 + ig + 16] * hv;
                p3 -= augA[o * 49 + 16 + ig + 24] * hv;
            }
            Ps[ig * P32 + j]        = p0;
            Ps[(ig + 8) * P32 + j]  = p1;
            Ps[(ig + 16) * P32 + j] = p2;
            Ps[(ig + 24) * P32 + j] = p3;
        }

        int conv = __syncthreads_and((int)(okl && (t > 0)));
        if (conv) {
            if (tid == 0) g_tconv = t;
            break;
        }
    }
}

// ---------------------------------------------------------------------------
// FALLBACK phase 2 (verified R6 path)
// ---------------------------------------------------------------------------
__global__ void __launch_bounds__(256, 1) phase2_kernel(
    const float* __restrict__ x0g,
    const float* __restrict__ meas,
    float* __restrict__ out)
{
    if (g_special) return;

    __shared__ float Wb[2][48 * SD];
    __shared__ float xs[8][2][SD + 1];
    __shared__ float zs[8][2][OD];

    const int tid  = threadIdx.x;
    const int bl   = tid >> 5;
    const int lane = tid & 31;
    const int b0   = (blockIdx.x * 8 + bl) * 2;
    const int b1   = b0 + 1;
    const int lzb  = (lane < OD) ? b0 : b1;
    const int lz   = lane & 15;
    const int tconv = g_tconv;

    xs[bl][0][lane] = x0g[b0 * SD + lane];
    xs[bl][1][lane] = x0g[b1 * SD + lane];
    zs[bl][lane >> 4][lz] = meas[(lzb * TT + 0) * OD + lz];
    {
        const float4* gw = (const float4*)g_W[0];
        float4* d = (float4*)Wb[0];
        d[tid] = gw[tid];
        if (tid < 128) d[256 + tid] = gw[256 + tid];
    }
    __syncthreads();

    int cur = 0;
    int tW = 0;

    #pragma unroll 1
    for (int t = 0; t < TT; t++) {
        int tn = (t + 1 < TT) ? ((t + 1 < tconv) ? (t + 1) : tconv) : tW;
        const bool stage = (tn != tW);

        float4 n0, n1;
        float zn;
        if (stage) {
            const float4* gw = (const float4*)g_W[tn];
            n0 = gw[tid];
            if (tid < 128) n1 = gw[256 + tid];
        }
        if (t + 1 < TT) zn = meas[(lzb * TT + (t + 1)) * OD + lz];

        const float* AT = Wb[cur];
        const float* KT = Wb[cur] + SD * SD;
        float a0 = 0.f, a1 = 0.f, c0 = 0.f, c1 = 0.f;
        #pragma unroll
        for (int j = 0; j < SD; j += 2) {
            float w0 = AT[j * SD + lane];
            float w1 = AT[(j + 1) * SD + lane];
            a0 += w0 * xs[bl][0][j];
            c0 += w0 * xs[bl][1][j];
            a1 += w1 * xs[bl][0][j + 1];
            c1 += w1 * xs[bl][1][j + 1];
        }
        #pragma unroll
        for (int o = 0; o < OD; o += 2) {
            float w0 = KT[o * SD + lane];
            float w1 = KT[(o + 1) * SD + lane];
            a0 += w0 * zs[bl][0][o];
            c0 += w0 * zs[bl][1][o];
            a1 += w1 * zs[bl][0][o + 1];
            c1 += w1 * zs[bl][1][o + 1];
        }
        const float xa = a0 + a1;
        const float xc = c0 + c1;
        out[(b0 * TT + t) * SD + lane] = xa;
        out[(b1 * TT + t) * SD + lane] = xc;
        __syncthreads();

        xs[bl][0][lane] = xa;
        xs[bl][1][lane] = xc;
        if (t + 1 < TT) zs[bl][lane >> 4][lz] = zn;
        if (stage) {
            float4* d = (float4*)Wb[cur ^ 1];
            d[tid] = n0;
            if (tid < 128) d[256 + tid] = n1;
            cur ^= 1;
            tW = tn;
        }
        __syncthreads();
    }
}

// ---------------------------------------------------------------------------
extern "C" void kernel_launch(void* const* d_in, const int* in_sizes, int n_in,
                              void* d_out, int out_size) {
    const float* state0 = (const float*)d_in[0];  // (B, 32)
    const float* cov0   = (const float*)d_in[1];  // (B, 32, 32)
    const float* meas   = (const float*)d_in[2];  // (B, 64, 16)
    const float* F      = (const float*)d_in[3];  // (32, 32)
    const float* H      = (const float*)d_in[4];  // (16, 32)
    const float* Q      = (const float*)d_in[5];  // (32, 32)
    const float* R      = (const float*)d_in[6];  // (16, 16)
    float* out = (float*)d_out;                   // (B, 64, 32)
    (void)in_sizes; (void)n_in; (void)out_size;

    prep_kernel<<<1, 256>>>(F, H, Q, R, cov0);
    phase1_kernel<<<1, 256>>>(F, H, Q, R, cov0);       // no-op if special
    phase2_new_kernel<<<NB / 8, 128>>>(state0, meas, out);  // no-op if !special
    phase2_kernel<<<NB / 16, 256>>>(state0, meas, out);     // no-op if special
}

// round 9
// speedup vs baseline: 7.3778x; 1.7518x over previous
#include <cuda_runtime.h>
#include <math.h>

// Kalman filter B=2048, T=64, STATE=32, OBS=16.
// SPECIAL PATH (F=I, Q=qI, R=rI, cov0=I — verified on device):
//   Riccati diagonalizes in SVD basis of H. prep_kernel: one-sided Jacobi SVD of H
//   + scalar gain recursions. phase2_new: per-batch 16 scalar scans + two matvecs.
// FALLBACK: previous verified phase1/phase2 (guarded by g_special).

#define SD 32
#define OD 16
#define TT 64
#define NB 2048
#define P32 33
#define P16 17

__device__ int g_special;
__device__ float g_U16[OD * OD];   // w_i = sum_m g_U16[i*16+m] * z_m   (U^T z)
__device__ float g_V[SD * OD];     // g_V[j*16+i] = V[j][i]
__device__ float g_ab[TT * 32];    // [t][i]=a_i,t  [t][16+i]=k_i,t

// fallback tables
__device__ __align__(16) float g_W[TT][48 * SD];
__device__ int g_tconv;

// ---------------------------------------------------------------------------
// prep: specialness check + Jacobi SVD (adaptive sweeps) + scalar gain recursion
// ---------------------------------------------------------------------------
__global__ void __launch_bounds__(256, 1) prep_kernel(
    const float* __restrict__ Fg, const float* __restrict__ Hg,
    const float* __restrict__ Qg, const float* __restrict__ Rg,
    const float* __restrict__ cov0)
{
    __shared__ float Hw[OD * 33];     // working copy of H (rows get rotated)
    __shared__ float Wacc[OD * 17];   // accumulated rotations
    __shared__ float sig[OD];
    __shared__ float qr[2];
    __shared__ int notconv;

    const int tid = threadIdx.x;
    const float q = Qg[0], r = Rg[0];
    if (tid == 0) { qr[0] = q; qr[1] = r; }

    bool ok = (r > 0.f) && (q >= 0.f);
    #pragma unroll
    for (int s = 0; s < 4; s++) {
        int e = tid + s * 256;
        int i = e >> 5, j = e & 31;
        float ide = (i == j) ? 1.f : 0.f;
        if (Fg[e] != ide) ok = false;
        if (cov0[e] != ide) ok = false;
        if (Qg[e] != ((i == j) ? q : 0.f)) ok = false;
    }
    {
        int i = tid >> 4, j = tid & 15;
        if (Rg[tid] != ((i == j) ? r : 0.f)) ok = false;
    }
    int special = __syncthreads_and((int)ok);
    if (tid == 0) g_special = special;
    if (!special) return;

    // init Hw = H, Wacc = I
    #pragma unroll
    for (int s = 0; s < 2; s++) {
        int e = tid + s * 256;
        Hw[(e >> 5) * 33 + (e & 31)] = Hg[e];
    }
    { int i = tid >> 4, m = tid & 15; Wacc[i * 17 + m] = (i == m) ? 1.f : 0.f; }
    __syncthreads();

    const int w = tid >> 5, lane = tid & 31;

    // one-sided Jacobi with adaptive sweep count
    for (int sweep = 0; sweep < 8; sweep++) {
        if (tid == 0) notconv = 0;
        __syncthreads();
        for (int rr = 0; rr < 15; rr++) {
            int p, qq;
            if (w == 0) { p = 0; qq = 1 + rr; }
            else { p = 1 + ((rr + w) % 15); qq = 1 + ((rr + 15 - w) % 15); }
            float hp = Hw[p * 33 + lane];
            float hq = Hw[qq * 33 + lane];
            float al = hp * hp, be = hq * hq, ga = hp * hq;
            #pragma unroll
            for (int off = 16; off; off >>= 1) {
                al += __shfl_xor_sync(0xffffffffu, al, off);
                be += __shfl_xor_sync(0xffffffffu, be, off);
                ga += __shfl_xor_sync(0xffffffffu, ga, off);
            }
            if (ga * ga > 1e-16f * al * be) {
                float tau = (be - al) / (2.f * ga);
                float tt = ((tau >= 0.f) ? 1.f : -1.f) / (fabsf(tau) + sqrtf(1.f + tau * tau));
                float c = rsqrtf(1.f + tt * tt);
                float s = c * tt;
                Hw[p * 33 + lane]  = c * hp - s * hq;
                Hw[qq * 33 + lane] = s * hp + c * hq;
                if (lane < OD) {
                    float up = Wacc[p * 17 + lane], uq = Wacc[qq * 17 + lane];
                    Wacc[p * 17 + lane]  = c * up - s * uq;
                    Wacc[qq * 17 + lane] = s * up + c * uq;
                }
            }
            if (lane == 0 && (ga * ga > 1e-14f * al * be)) notconv = 1;
            __syncthreads();
        }
        if (!notconv) break;
        __syncthreads();
    }

    // row norms -> sigma
    {
        int row0 = w * 2;
        #pragma unroll
        for (int rep = 0; rep < 2; rep++) {
            int row = row0 + rep;
            float v = Hw[row * 33 + lane];
            float ss = v * v;
            #pragma unroll
            for (int off = 16; off; off >>= 1) ss += __shfl_xor_sync(0xffffffffu, ss, off);
            if (lane == 0) sig[row] = sqrtf(ss);
        }
    }
    __syncthreads();

    // V[j][i] = Hw[i][j]/sigma_i ; U^T rows = Wacc rows
    #pragma unroll
    for (int s = 0; s < 2; s++) {
        int e = tid + s * 256;       // 512
        int j = e >> 4, i = e & 15;
        float sg = sig[i];
        float rsg = (sg > 1e-20f) ? (1.f / sg) : 0.f;
        g_V[j * 16 + i] = Hw[i * 33 + j] * rsg;
    }
    { int i = tid >> 4, m = tid & 15; g_U16[i * 16 + m] = Wacc[i * 17 + m]; }

    // scalar gain recursion per component
    if (tid < OD) {
        float sg = sig[tid];
        float lam = sg * sg;
        float p = 1.f;
        const float qv = qr[0], rv = qr[1];
        for (int t = 0; t < TT; t++) {
            float pp = p + qv;
            float dinv = 1.f / (lam * pp + rv);
            float a = rv * dinv;
            float kk = pp * sg * dinv;
            g_ab[t * 32 + tid] = a;
            g_ab[t * 32 + 16 + tid] = kk;
            p = a * pp;
        }
    }
}

// ---------------------------------------------------------------------------
// phase2 special: 8 warps/CTA, 1 batch/warp, 256 CTAs. float4 LDS broadcasts.
// w = U^T z (in-place, 1 syncwarp/iter); scalar scans; x = u + V y.
// ---------------------------------------------------------------------------
__global__ void __launch_bounds__(256, 1) phase2_new_kernel(
    const float* __restrict__ x0g,
    const float* __restrict__ meas,   // (B, T, 16)
    float* __restrict__ out)          // (B, T, 32)
{
    if (!g_special) return;

    __shared__ float4 zb[8][TT * OD / 4];  // 8 warps x 4KB: z -> w -> y in place
    __shared__ float2 ab2[TT * OD];        // (a_i,t , k_i,t)
    __shared__ float Us[OD * OD];
    __shared__ float Vs[SD * 17];

    const int tid  = threadIdx.x;
    const int w    = tid >> 5;
    const int lane = tid & 31;
    const int i16  = lane & 15;

    // stage constants
    for (int e = tid; e < TT * OD; e += 256) {
        int t = e >> 4, i = e & 15;
        ab2[e] = make_float2(g_ab[t * 32 + i], g_ab[t * 32 + 16 + i]);
    }
    if (tid < OD * OD) Us[tid] = g_U16[tid];
    for (int e = tid; e < SD * OD; e += 256) Vs[(e >> 4) * 17 + (e & 15)] = g_V[e];
    __syncthreads();

    float Ureg[16], Vreg[16];
    #pragma unroll
    for (int m = 0; m < 16; m++) Ureg[m] = Us[i16 * 16 + m];
    #pragma unroll
    for (int m = 0; m < 16; m++) Vreg[m] = Vs[lane * 17 + m];

    const int b = blockIdx.x * 8 + w;
    float4* zw = zb[w];

    // load z tile (1024 floats = 256 float4, coalesced)
    const float4* zg = (const float4*)(meas + (size_t)b * TT * OD);
    #pragma unroll
    for (int it = 0; it < 8; it++) zw[it * 32 + lane] = zg[it * 32 + lane];
    float x0reg = x0g[b * SD + lane];
    __syncwarp();

    // w[t] = U^T z[t], in place. iter it handles rows 2it (lanes 0-15), 2it+1 (16-31).
    #pragma unroll 4
    for (int it = 0; it < 32; it++) {
        const int t = it * 2 + (lane >> 4);
        float4 z0 = zw[t * 4 + 0];
        float4 z1 = zw[t * 4 + 1];
        float4 z2 = zw[t * 4 + 2];
        float4 z3 = zw[t * 4 + 3];
        float acc = Ureg[0] * z0.x + Ureg[1] * z0.y + Ureg[2] * z0.z + Ureg[3] * z0.w
                  + Ureg[4] * z1.x + Ureg[5] * z1.y + Ureg[6] * z1.z + Ureg[7] * z1.w
                  + Ureg[8] * z2.x + Ureg[9] * z2.y + Ureg[10] * z2.z + Ureg[11] * z2.w
                  + Ureg[12] * z3.x + Ureg[13] * z3.y + Ureg[14] * z3.z + Ureg[15] * z3.w;
        __syncwarp();              // all reads of rows 2it,2it+1 complete
        ((float*)zw)[t * 16 + i16] = acc;
        // next iteration reads different rows; no second sync needed
    }
    __syncwarp();

    // y0 = V^T x0 (component i16, duplicated across half-warps)
    float y = 0.f;
    #pragma unroll
    for (int j = 0; j < 32; j++)
        y += Vs[j * 17 + i16] * __shfl_sync(0xffffffffu, x0reg, j);

    // u[j] = x0[j] - sum_i V[j][i] y0_i
    float u = x0reg;
    #pragma unroll
    for (int m = 0; m < 16; m++)
        u -= Vreg[m] * __shfl_sync(0xffffffffu, y, m);

    // scalar scans: y_t = a y + k w, overwrite w with y (lanes 0..15)
    if (lane < 16) {
        float* yw = (float*)zw;
        #pragma unroll 1
        for (int t = 0; t < TT; t++) {
            float2 akv = ab2[t * 16 + i16];
            float wv = yw[t * 16 + i16];
            y = akv.x * y + akv.y * wv;
            yw[t * 16 + i16] = y;
        }
    }
    __syncwarp();

    // out[t][j] = u[j] + sum_i V[j][i] y[t][i]   (float4 broadcasts of y rows)
    float* ob = out + (size_t)b * TT * SD;
    #pragma unroll 2
    for (int t = 0; t < TT; t++) {
        float4 y0 = zw[t * 4 + 0];
        float4 y1 = zw[t * 4 + 1];
        float4 y2 = zw[t * 4 + 2];
        float4 y3 = zw[t * 4 + 3];
        float acc = u
                  + Vreg[0] * y0.x + Vreg[1] * y0.y + Vreg[2] * y0.z + Vreg[3] * y0.w
                  + Vreg[4] * y1.x + Vreg[5] * y1.y + Vreg[6] * y1.z + Vreg[7] * y1.w
                  + Vreg[8] * y2.x + Vreg[9] * y2.y + Vreg[10] * y2.z + Vreg[11] * y2.w
                  + Vreg[12] * y3.x + Vreg[13] * y3.y + Vreg[14] * y3.z + Vreg[15] * y3.w;
        ob[t * SD + lane] = acc;
    }
}

// ---------------------------------------------------------------------------
// FALLBACK phase 1 (verified R6 path)
// ---------------------------------------------------------------------------
__global__ void __launch_bounds__(256, 1) phase1_kernel(
    const float* __restrict__ Fg, const float* __restrict__ Hg,
    const float* __restrict__ Qg, const float* __restrict__ Rg,
    const float* __restrict__ cov0)
{
    if (g_special) return;

    __shared__ float Fs[SD * P32];
    __shared__ float FT[SD * P32];
    __shared__ float Qs[SD * P32];
    __shared__ float Hs[OD * P32];
    __shared__ float Rs[OD * P16];
    __shared__ float Gs[OD * P32];
    __shared__ float Ps[SD * P32];
    __shared__ float Pp[SD * P32];
    __shared__ float T1[SD * P32];
    __shared__ float HPs[OD * P32];
    __shared__ float augA[OD * 49];
    __shared__ float augB[OD * 49];
    __shared__ float KPrev[OD * SD];
    __shared__ int fid;

    const int tid  = threadIdx.x;
    const int wid  = tid >> 5;
    const int lane = tid & 31;
    const int half = lane >> 4;
    const int rsel = wid + 8 * half;

    if (tid == 0) { fid = 1; g_tconv = TT - 1; }
    __syncthreads();

    {
        bool ok = true;
        #pragma unroll
        for (int s = 0; s < 4; s++) {
            int e = tid + s * 256;
            int i = e >> 5, j = e & 31;
            float f = Fg[e];
            Fs[i * P32 + j] = f;
            FT[j * P32 + i] = f;
            Qs[i * P32 + j] = Qg[e];
            Ps[i * P32 + j] = cov0[e];
            if (f != ((i == j) ? 1.0f : 0.0f)) ok = false;
        }
        if (!ok) fid = 0;
        #pragma unroll
        for (int s = 0; s < 2; s++) {
            int e = tid + s * 256;
            Hs[(e >> 5) * P32 + (e & 31)] = Hg[e];
        }
        Rs[(tid >> 4) * P16 + (tid & 15)] = Rg[tid];
    }
    __syncthreads();

    float hsel[SD];
    #pragma unroll
    for (int k = 0; k < SD; k++) hsel[k] = Hs[rsel * P32 + k];

    #pragma unroll
    for (int s = 0; s < 2; s++) {
        int e = tid + s * 256;
        int o = e >> 5, j = e & 31;
        float acc = 0.f;
        #pragma unroll
        for (int k = 0; k < SD; k++) acc += Hs[o * P32 + k] * FT[j * P32 + k];
        Gs[o * P32 + j] = acc;
    }
    const int ident = fid;
    __syncthreads();

    float Greg[OD * 4];
    #pragma unroll
    for (int o = 0; o < OD; o++) {
        Greg[o * 4 + 0] = Gs[o * P32 + wid];
        Greg[o * 4 + 1] = Gs[o * P32 + wid + 8];
        Greg[o * 4 + 2] = Gs[o * P32 + wid + 16];
        Greg[o * 4 + 3] = Gs[o * P32 + wid + 24];
    }

    #pragma unroll 1
    for (int t = 0; t < TT; t++) {
        if (ident) {
            #pragma unroll
            for (int s = 0; s < 4; s++) {
                int e = tid + s * 256;
                int idx = (e >> 5) * P32 + (e & 31);
                Pp[idx] = Ps[idx] + Qs[idx];
            }
        } else {
            #pragma unroll
            for (int s = 0; s < 4; s++) {
                int e = tid + s * 256;
                int i = e >> 5, j = e & 31;
                float acc = 0.f;
                #pragma unroll
                for (int k = 0; k < SD; k++) acc += Fs[i * P32 + k] * Ps[k * P32 + j];
                T1[i * P32 + j] = acc;
            }
            __syncthreads();
            #pragma unroll
            for (int s = 0; s < 4; s++) {
                int e = tid + s * 256;
                int i = e >> 5, j = e & 31;
                float acc = Qs[i * P32 + j];
                #pragma unroll
                for (int k = 0; k < SD; k++) acc += T1[i * P32 + k] * Fs[j * P32 + k];
                Pp[i * P32 + j] = acc;
            }
        }
        __syncthreads();

        {
            const int j0 = lane & 15;
            float a0 = 0.f, a1 = 0.f;
            #pragma unroll
            for (int k = 0; k < SD; k++) {
                float p0 = Pp[k * P32 + j0];
                float p1 = Pp[k * P32 + j0 + 16];
                a0 += hsel[k] * p0;
                a1 += hsel[k] * p1;
            }
            HPs[rsel * P32 + j0]      = a0;
            HPs[rsel * P32 + j0 + 16] = a1;
        }
        __syncthreads();

        {
            const int rr = lane & 15;
            float acc = Rs[rr * P16 + rsel];
            #pragma unroll
            for (int k = 0; k < SD; k++) acc += HPs[rr * P32 + k] * hsel[k];
            augA[rr * 49 + rsel] = acc;
        }
        #pragma unroll
        for (int s = 0; s < 2; s++) {
            int e = tid + s * 256;
            int rr = e >> 5, i = e & 31;
            augA[rr * 49 + 16 + i] = HPs[rr * P32 + i];
        }
        __syncthreads();

        #pragma unroll 1
        for (int rd = 0; rd < 8; rd++) {
            const float* cu = (rd & 1) ? augB : augA;
            float* nx = (rd & 1) ? augA : augB;
            const int p = 2 * rd;
            const float a  = cu[p * 49 + p];
            const float bb = cu[p * 49 + p + 1];
            const float cc = cu[(p + 1) * 49 + p];
            const float dd = cu[(p + 1) * 49 + p + 1];
            const float rdet = 1.0f / (a * dd - bb * cc);
            const int aw = 46 - 2 * rd;
            const int cb = p + 2;
            const int tot = OD * aw;
            for (int e = tid; e < tot; e += 256) {
                int rr = e / aw;
                int c = cb + (e - rr * aw);
                float rp = cu[p * 49 + c];
                float rq = cu[(p + 1) * 49 + c];
                float np = (dd * rp - bb * rq) * rdet;
                float nq = (a * rq - cc * rp) * rdet;
                float val;
                if (rr == p)          val = np;
                else if (rr == p + 1) val = nq;
                else                  val = cu[rr * 49 + c] - cu[rr * 49 + p] * np - cu[rr * 49 + p + 1] * nq;
                nx[rr * 49 + c] = val;
            }
            __syncthreads();
        }

        bool okl = true;
        #pragma unroll
        for (int s = 0; s < 2; s++) {
            int e = tid + s * 256;
            int o = e >> 5, i = e & 31;
            float kv = augA[o * 49 + 16 + i];
            g_W[t][(SD + o) * SD + i] = kv;
            float pv = KPrev[e];
            KPrev[e] = kv;
            if (fabsf(kv - pv) >= 3e-6f) okl = false;
        }

        {
            const int i = lane, jg = wid;
            float w0 = FT[jg * P32 + i];
            float w1 = FT[(jg + 8) * P32 + i];
            float w2 = FT[(jg + 16) * P32 + i];
            float w3 = FT[(jg + 24) * P32 + i];
            #pragma unroll
            for (int o = 0; o < OD; o++) {
                float kv = augA[o * 49 + 16 + i];
                w0 -= Greg[o * 4 + 0] * kv;
                w1 -= Greg[o * 4 + 1] * kv;
                w2 -= Greg[o * 4 + 2] * kv;
                w3 -= Greg[o * 4 + 3] * kv;
            }
            float* wt = g_W[t];
            wt[jg * SD + i]        = w0;
            wt[(jg + 8) * SD + i]  = w1;
            wt[(jg + 16) * SD + i] = w2;
            wt[(jg + 24) * SD + i] = w3;
        }

        {
            const int j = lane, ig = wid;
            float p0 = Pp[ig * P32 + j];
            float p1 = Pp[(ig + 8) * P32 + j];
            float p2 = Pp[(ig + 16) * P32 + j];
            float p3 = Pp[(ig + 24) * P32 + j];
            #pragma unroll
            for (int o = 0; o < OD; o++) {
                float hv = HPs[o * P32 + j];
                p0 -= augA[o * 49 + 16 + ig] * hv;
                p1 -= augA[o * 49 + 16 + ig + 8] * hv;
                p2 -= augA[o * 49 + 16 + ig + 16] * hv;
                p3 -= augA[o * 49 + 16 + ig + 24] * hv;
            }
            Ps[ig * P32 + j]        = p0;
            Ps[(ig + 8) * P32 + j]  = p1;
            Ps[(ig + 16) * P32 + j] = p2;
            Ps[(ig + 24) * P32 + j] = p3;
        }

        int conv = __syncthreads_and((int)(okl && (t > 0)));
        if (conv) {
            if (tid == 0) g_tconv = t;
            break;
        }
    }
}

// ---------------------------------------------------------------------------
// FALLBACK phase 2 (verified R6 path)
// ---------------------------------------------------------------------------
__global__ void __launch_bounds__(256, 1) phase2_kernel(
    const float* __restrict__ x0g,
    const float* __restrict__ meas,
    float* __restrict__ out)
{
    if (g_special) return;

    __shared__ float Wb[2][48 * SD];
    __shared__ float xs[8][2][SD + 1];
    __shared__ float zs[8][2][OD];

    const int tid  = threadIdx.x;
    const int bl   = tid >> 5;
    const int lane = tid & 31;
    const int b0   = (blockIdx.x * 8 + bl) * 2;
    const int b1   = b0 + 1;
    const int lzb  = (lane < OD) ? b0 : b1;
    const int lz   = lane & 15;
    const int tconv = g_tconv;

    xs[bl][0][lane] = x0g[b0 * SD + lane];
    xs[bl][1][lane] = x0g[b1 * SD + lane];
    zs[bl][lane >> 4][lz] = meas[(lzb * TT + 0) * OD + lz];
    {
        const float4* gw = (const float4*)g_W[0];
        float4* d = (float4*)Wb[0];
        d[tid] = gw[tid];
        if (tid < 128) d[256 + tid] = gw[256 + tid];
    }
    __syncthreads();

    int cur = 0;
    int tW = 0;

    #pragma unroll 1
    for (int t = 0; t < TT; t++) {
        int tn = (t + 1 < TT) ? ((t + 1 < tconv) ? (t + 1) : tconv) : tW;
        const bool stage = (tn != tW);

        float4 n0, n1;
        float zn;
        if (stage) {
            const float4* gw = (const float4*)g_W[tn];
            n0 = gw[tid];
            if (tid < 128) n1 = gw[256 + tid];
        }
        if (t + 1 < TT) zn = meas[(lzb * TT + (t + 1)) * OD + lz];

        const float* AT = Wb[cur];
        const float* KT = Wb[cur] + SD * SD;
        float a0 = 0.f, a1 = 0.f, c0 = 0.f, c1 = 0.f;
        #pragma unroll
        for (int j = 0; j < SD; j += 2) {
            float w0 = AT[j * SD + lane];
            float w1 = AT[(j + 1) * SD + lane];
            a0 += w0 * xs[bl][0][j];
            c0 += w0 * xs[bl][1][j];
            a1 += w1 * xs[bl][0][j + 1];
            c1 += w1 * xs[bl][1][j + 1];
        }
        #pragma unroll
        for (int o = 0; o < OD; o += 2) {
            float w0 = KT[o * SD + lane];
            float w1 = KT[(o + 1) * SD + lane];
            a0 += w0 * zs[bl][0][o];
            c0 += w0 * zs[bl][1][o];
            a1 += w1 * zs[bl][0][o + 1];
            c1 += w1 * zs[bl][1][o + 1];
        }
        const float xa = a0 + a1;
        const float xc = c0 + c1;
        out[(b0 * TT + t) * SD + lane] = xa;
        out[(b1 * TT + t) * SD + lane] = xc;
        __syncthreads();

        xs[bl][0][lane] = xa;
        xs[bl][1][lane] = xc;
        if (t + 1 < TT) zs[bl][lane >> 4][lz] = zn;
        if (stage) {
            float4* d = (float4*)Wb[cur ^ 1];
            d[tid] = n0;
            if (tid < 128) d[256 + tid] = n1;
            cur ^= 1;
            tW = tn;
        }
        __syncthreads();
    }
}

// ---------------------------------------------------------------------------
extern "C" void kernel_launch(void* const* d_in, const int* in_sizes, int n_in,
                              void* d_out, int out_size) {
    const float* state0 = (const float*)d_in[0];  // (B, 32)
    const float* cov0   = (const float*)d_in[1];  // (B, 32, 32)
    const float* meas   = (const float*)d_in[2];  // (B, 64, 16)
    const float* F      = (const float*)d_in[3];  // (32, 32)
    const float* H      = (const float*)d_in[4];  // (16, 32)
    const float* Q      = (const float*)d_in[5];  // (32, 32)
    const float* R      = (const float*)d_in[6];  // (16, 16)
    float* out = (float*)d_out;                   // (B, 64, 32)
    (void)in_sizes; (void)n_in; (void)out_size;

    prep_kernel<<<1, 256>>>(F, H, Q, R, cov0);
    phase1_kernel<<<1, 256>>>(F, H, Q, R, cov0);            // no-op if special
    phase2_new_kernel<<<NB / 8, 256>>>(state0, meas, out);  // no-op if !special
    phase2_kernel<<<NB / 16, 256>>>(state0, meas, out);     // no-op if special
}

// round 10
// speedup vs baseline: 7.4097x; 1.0043x over previous
#include <cuda_runtime.h>
#include <math.h>

// Kalman filter B=2048, T=64, STATE=32, OBS=16.
// SPECIAL PATH (F=I, Q=qI, R=rI, cov0=I — verified per CTA):
//   fused_kernel: every CTA (128 x 512thr) redundantly runs Jacobi SVD of H +
//   scalar gain recursions in its own smem, then 16 warps each filter one batch
//   via 16 decoupled scalar scans. No global tables, no prep kernel.
// FALLBACK: verified phase1/phase2 (phase1 performs the specialness check and
//   publishes g_special; both are no-ops on special inputs).

#define SD 32
#define OD 16
#define TT 64
#define NB 2048
#define P32 33
#define P16 17

__device__ int g_special;
__device__ __align__(16) float g_W[TT][48 * SD];
__device__ int g_tconv;

// ---------------------------------------------------------------------------
// Fused special-path kernel: per-CTA prep + per-warp batch scans.
// ---------------------------------------------------------------------------
__global__ void __launch_bounds__(512, 1) fused_kernel(
    const float* __restrict__ x0g,
    const float* __restrict__ meas,   // (B, T, 16)
    float* __restrict__ out,          // (B, T, 32)
    const float* __restrict__ Fg, const float* __restrict__ Hg,
    const float* __restrict__ Qg, const float* __restrict__ Rg,
    const float* __restrict__ cov0)
{
    extern __shared__ float4 zb_dyn[];      // [16][256] float4 = 64KB

    __shared__ float Hw[OD * 33];
    __shared__ float Wacc[OD * 17];
    __shared__ float sig[OD];
    __shared__ float2 ab2[TT * OD];         // (a_i,t , k_i,t)
    __shared__ float Us[OD * OD];
    __shared__ float Vs[SD * 17];
    __shared__ int notconv;

    const int tid  = threadIdx.x;
    const int w    = tid >> 5;
    const int lane = tid & 31;
    const int i16  = lane & 15;
    const float q = Qg[0], r = Rg[0];

    // ---- specialness check (all 512 threads) ----
    {
        bool ok = (r > 0.f) && (q >= 0.f);
        #pragma unroll
        for (int s = 0; s < 2; s++) {
            int e = tid + s * 512;
            int i = e >> 5, j = e & 31;
            float ide = (i == j) ? 1.f : 0.f;
            if (Fg[e] != ide) ok = false;
            if (cov0[e] != ide) ok = false;
            if (Qg[e] != ((i == j) ? q : 0.f)) ok = false;
        }
        if (tid < 256) {
            int i = tid >> 4, j = tid & 15;
            if (Rg[tid] != ((i == j) ? r : 0.f)) ok = false;
        }
        int special = __syncthreads_and((int)ok);
        if (!special) return;    // fallback kernels handle it
    }

    // ---- init Hw = H, Wacc = I ----
    {
        int i = tid >> 5, j = tid & 31;
        Hw[i * 33 + j] = Hg[tid];
    }
    if (tid < 256) {
        int i = tid >> 4, m = tid & 15;
        Wacc[i * 17 + m] = (i == m) ? 1.f : 0.f;
    }
    __syncthreads();

    // ---- one-sided Jacobi (warps 0..7 active), adaptive sweeps ----
    for (int sweep = 0; sweep < 8; sweep++) {
        if (tid == 0) notconv = 0;
        __syncthreads();
        for (int rr = 0; rr < 15; rr++) {
            if (w < 8) {
                int p, qq;
                if (w == 0) { p = 0; qq = 1 + rr; }
                else { p = 1 + ((rr + w) % 15); qq = 1 + ((rr + 15 - w) % 15); }
                float hp = Hw[p * 33 + lane];
                float hq = Hw[qq * 33 + lane];
                float al = hp * hp, be = hq * hq, ga = hp * hq;
                #pragma unroll
                for (int off = 16; off; off >>= 1) {
                    al += __shfl_xor_sync(0xffffffffu, al, off);
                    be += __shfl_xor_sync(0xffffffffu, be, off);
                    ga += __shfl_xor_sync(0xffffffffu, ga, off);
                }
                if (ga * ga > 1e-16f * al * be) {
                    float tau = (be - al) / (2.f * ga);
                    float tt = ((tau >= 0.f) ? 1.f : -1.f) / (fabsf(tau) + sqrtf(1.f + tau * tau));
                    float c = rsqrtf(1.f + tt * tt);
                    float s = c * tt;
                    Hw[p * 33 + lane]  = c * hp - s * hq;
                    Hw[qq * 33 + lane] = s * hp + c * hq;
                    if (lane < OD) {
                        float up = Wacc[p * 17 + lane], uq = Wacc[qq * 17 + lane];
                        Wacc[p * 17 + lane]  = c * up - s * uq;
                        Wacc[qq * 17 + lane] = s * up + c * uq;
                    }
                }
                if (lane == 0 && (ga * ga > 1e-14f * al * be)) notconv = 1;
            }
            __syncthreads();
        }
        if (!notconv) break;
        __syncthreads();
    }

    // ---- row norms -> sigma (warps 0..7) ----
    if (w < 8) {
        int row0 = w * 2;
        #pragma unroll
        for (int rep = 0; rep < 2; rep++) {
            int row = row0 + rep;
            float v = Hw[row * 33 + lane];
            float ss = v * v;
            #pragma unroll
            for (int off = 16; off; off >>= 1) ss += __shfl_xor_sync(0xffffffffu, ss, off);
            if (lane == 0) sig[row] = sqrtf(ss);
        }
    }
    __syncthreads();

    // ---- Vs[j][i] = Hw[i][j]/sigma_i ; Us = Wacc (U^T) ----
    {
        int j = tid >> 4, i = tid & 15;
        float sg = sig[i];
        float rsg = (sg > 1e-20f) ? (1.f / sg) : 0.f;
        Vs[j * 17 + i] = Hw[i * 33 + j] * rsg;
    }
    if (tid < 256) Us[tid] = Wacc[(tid >> 4) * 17 + (tid & 15)];

    // ---- scalar gain recursion (threads 0..15) ----
    if (tid < OD) {
        float sg = sig[tid];
        float lam = sg * sg;
        float p = 1.f;
        #pragma unroll 1
        for (int t = 0; t < TT; t++) {
            float pp = p + q;
            float dinv = 1.f / (lam * pp + r);
            float a = r * dinv;
            float kk = pp * sg * dinv;
            ab2[t * 16 + tid] = make_float2(a, kk);
            p = a * pp;
        }
    }
    __syncthreads();

    // ---- per-warp batch filter ----
    float Ureg[16], Vreg[16];
    #pragma unroll
    for (int m = 0; m < 16; m++) Ureg[m] = Us[i16 * 16 + m];
    #pragma unroll
    for (int m = 0; m < 16; m++) Vreg[m] = Vs[lane * 17 + m];

    const int b = blockIdx.x * 16 + w;
    float4* zw = zb_dyn + w * (TT * OD / 4);

    // load z tile (1024 floats = 256 float4, coalesced)
    const float4* zg = (const float4*)(meas + (size_t)b * TT * OD);
    #pragma unroll
    for (int it = 0; it < 8; it++) zw[it * 32 + lane] = zg[it * 32 + lane];
    float x0reg = x0g[b * SD + lane];
    __syncwarp();

    // w[t] = U^T z[t], in place; iter handles rows 2it (lanes 0-15), 2it+1 (16-31)
    #pragma unroll 4
    for (int it = 0; it < 32; it++) {
        const int t = it * 2 + (lane >> 4);
        float4 z0 = zw[t * 4 + 0];
        float4 z1 = zw[t * 4 + 1];
        float4 z2 = zw[t * 4 + 2];
        float4 z3 = zw[t * 4 + 3];
        float acc = Ureg[0] * z0.x + Ureg[1] * z0.y + Ureg[2] * z0.z + Ureg[3] * z0.w
                  + Ureg[4] * z1.x + Ureg[5] * z1.y + Ureg[6] * z1.z + Ureg[7] * z1.w
                  + Ureg[8] * z2.x + Ureg[9] * z2.y + Ureg[10] * z2.z + Ureg[11] * z2.w
                  + Ureg[12] * z3.x + Ureg[13] * z3.y + Ureg[14] * z3.z + Ureg[15] * z3.w;
        __syncwarp();
        ((float*)zw)[t * 16 + i16] = acc;
    }
    __syncwarp();

    // y0 = V^T x0 (component i16, duplicated across half-warps)
    float y = 0.f;
    #pragma unroll
    for (int j = 0; j < 32; j++)
        y += Vs[j * 17 + i16] * __shfl_sync(0xffffffffu, x0reg, j);

    // u[j] = x0[j] - sum_i V[j][i] y0_i
    float u = x0reg;
    #pragma unroll
    for (int m = 0; m < 16; m++)
        u -= Vreg[m] * __shfl_sync(0xffffffffu, y, m);

    // scalar scans: y_t = a y + k w (lanes 0..15), overwrite w with y
    if (lane < 16) {
        float* yw = (float*)zw;
        #pragma unroll 1
        for (int t = 0; t < TT; t++) {
            float2 akv = ab2[t * 16 + i16];
            float wv = yw[t * 16 + i16];
            y = akv.x * y + akv.y * wv;
            yw[t * 16 + i16] = y;
        }
    }
    __syncwarp();

    // out[t][j] = u[j] + sum_i V[j][i] y[t][i]
    float* ob = out + (size_t)b * TT * SD;
    #pragma unroll 2
    for (int t = 0; t < TT; t++) {
        float4 y0 = zw[t * 4 + 0];
        float4 y1 = zw[t * 4 + 1];
        float4 y2 = zw[t * 4 + 2];
        float4 y3 = zw[t * 4 + 3];
        float acc = u
                  + Vreg[0] * y0.x + Vreg[1] * y0.y + Vreg[2] * y0.z + Vreg[3] * y0.w
                  + Vreg[4] * y1.x + Vreg[5] * y1.y + Vreg[6] * y1.z + Vreg[7] * y1.w
                  + Vreg[8] * y2.x + Vreg[9] * y2.y + Vreg[10] * y2.z + Vreg[11] * y2.w
                  + Vreg[12] * y3.x + Vreg[13] * y3.y + Vreg[14] * y3.z + Vreg[15] * y3.w;
        ob[t * SD + lane] = acc;
    }
}

// ---------------------------------------------------------------------------
// FALLBACK phase 1 (verified R6 path) — also performs the specialness check
// and publishes g_special for phase2_kernel. No-op (early return) if special.
// ---------------------------------------------------------------------------
__global__ void __launch_bounds__(256, 1) phase1_kernel(
    const float* __restrict__ Fg, const float* __restrict__ Hg,
    const float* __restrict__ Qg, const float* __restrict__ Rg,
    const float* __restrict__ cov0)
{
    __shared__ float Fs[SD * P32];
    __shared__ float FT[SD * P32];
    __shared__ float Qs[SD * P32];
    __shared__ float Hs[OD * P32];
    __shared__ float Rs[OD * P16];
    __shared__ float Gs[OD * P32];
    __shared__ float Ps[SD * P32];
    __shared__ float Pp[SD * P32];
    __shared__ float T1[SD * P32];
    __shared__ float HPs[OD * P32];
    __shared__ float augA[OD * 49];
    __shared__ float augB[OD * 49];
    __shared__ float KPrev[OD * SD];
    __shared__ int fid;

    const int tid  = threadIdx.x;
    const int wid  = tid >> 5;
    const int lane = tid & 31;
    const int half = lane >> 4;
    const int rsel = wid + 8 * half;

    if (tid == 0) { fid = 1; g_tconv = TT - 1; }
    __syncthreads();

    const float q = Qg[0], r = Rg[0];
    {
        bool okF = true;
        bool okSp = (r > 0.f) && (q >= 0.f);
        #pragma unroll
        for (int s = 0; s < 4; s++) {
            int e = tid + s * 256;
            int i = e >> 5, j = e & 31;
            float ide = (i == j) ? 1.0f : 0.0f;
            float f = Fg[e];
            Fs[i * P32 + j] = f;
            FT[j * P32 + i] = f;
            Qs[i * P32 + j] = Qg[e];
            Ps[i * P32 + j] = cov0[e];
            if (f != ide) okF = false;
            if (Qg[e] != ((i == j) ? q : 0.f)) okSp = false;
            if (cov0[e] != ide) okSp = false;
        }
        if (!okF) fid = 0;
        #pragma unroll
        for (int s = 0; s < 2; s++) {
            int e = tid + s * 256;
            Hs[(e >> 5) * P32 + (e & 31)] = Hg[e];
        }
        Rs[(tid >> 4) * P16 + (tid & 15)] = Rg[tid];
        {
            int i = tid >> 4, j = tid & 15;
            if (Rg[tid] != ((i == j) ? r : 0.f)) okSp = false;
        }
        int special = __syncthreads_and((int)(okF && okSp));
        if (tid == 0) g_special = special;
        if (special) return;   // fused kernel handled the output
    }
    __syncthreads();

    float hsel[SD];
    #pragma unroll
    for (int k = 0; k < SD; k++) hsel[k] = Hs[rsel * P32 + k];

    #pragma unroll
    for (int s = 0; s < 2; s++) {
        int e = tid + s * 256;
        int o = e >> 5, j = e & 31;
        float acc = 0.f;
        #pragma unroll
        for (int k = 0; k < SD; k++) acc += Hs[o * P32 + k] * FT[j * P32 + k];
        Gs[o * P32 + j] = acc;
    }
    const int ident = fid;
    __syncthreads();

    float Greg[OD * 4];
    #pragma unroll
    for (int o = 0; o < OD; o++) {
        Greg[o * 4 + 0] = Gs[o * P32 + wid];
        Greg[o * 4 + 1] = Gs[o * P32 + wid + 8];
        Greg[o * 4 + 2] = Gs[o * P32 + wid + 16];
        Greg[o * 4 + 3] = Gs[o * P32 + wid + 24];
    }

    #pragma unroll 1
    for (int t = 0; t < TT; t++) {
        if (ident) {
            #pragma unroll
            for (int s = 0; s < 4; s++) {
                int e = tid + s * 256;
                int idx = (e >> 5) * P32 + (e & 31);
                Pp[idx] = Ps[idx] + Qs[idx];
            }
        } else {
            #pragma unroll
            for (int s = 0; s < 4; s++) {
                int e = tid + s * 256;
                int i = e >> 5, j = e & 31;
                float acc = 0.f;
                #pragma unroll
                for (int k = 0; k < SD; k++) acc += Fs[i * P32 + k] * Ps[k * P32 + j];
                T1[i * P32 + j] = acc;
            }
            __syncthreads();
            #pragma unroll
            for (int s = 0; s < 4; s++) {
                int e = tid + s * 256;
                int i = e >> 5, j = e & 31;
                float acc = Qs[i * P32 + j];
                #pragma unroll
                for (int k = 0; k < SD; k++) acc += T1[i * P32 + k] * Fs[j * P32 + k];
                Pp[i * P32 + j] = acc;
            }
        }
        __syncthreads();

        {
            const int j0 = lane & 15;
            float a0 = 0.f, a1 = 0.f;
            #pragma unroll
            for (int k = 0; k < SD; k++) {
                float p0 = Pp[k * P32 + j0];
                float p1 = Pp[k * P32 + j0 + 16];
                a0 += hsel[k] * p0;
                a1 += hsel[k] * p1;
            }
            HPs[rsel * P32 + j0]      = a0;
            HPs[rsel * P32 + j0 + 16] = a1;
        }
        __syncthreads();

        {
            const int rr = lane & 15;
            float acc = Rs[rr * P16 + rsel];
            #pragma unroll
            for (int k = 0; k < SD; k++) acc += HPs[rr * P32 + k] * hsel[k];
            augA[rr * 49 + rsel] = acc;
        }
        #pragma unroll
        for (int s = 0; s < 2; s++) {
            int e = tid + s * 256;
            int rr = e >> 5, i = e & 31;
            augA[rr * 49 + 16 + i] = HPs[rr * P32 + i];
        }
        __syncthreads();

        #pragma unroll 1
        for (int rd = 0; rd < 8; rd++) {
            const float* cu = (rd & 1) ? augB : augA;
            float* nx = (rd & 1) ? augA : augB;
            const int p = 2 * rd;
            const float a  = cu[p * 49 + p];
            const float bb = cu[p * 49 + p + 1];
            const float cc = cu[(p + 1) * 49 + p];
            const float dd = cu[(p + 1) * 49 + p + 1];
            const float rdet = 1.0f / (a * dd - bb * cc);
            const int aw = 46 - 2 * rd;
            const int cb = p + 2;
            const int tot = OD * aw;
            for (int e = tid; e < tot; e += 256) {
                int rr = e / aw;
                int c = cb + (e - rr * aw);
                float rp = cu[p * 49 + c];
                float rq = cu[(p + 1) * 49 + c];
                float np = (dd * rp - bb * rq) * rdet;
                float nq = (a * rq - cc * rp) * rdet;
                float val;
                if (rr == p)          val = np;
                else if (rr == p + 1) val = nq;
                else                  val = cu[rr * 49 + c] - cu[rr * 49 + p] * np - cu[rr * 49 + p + 1] * nq;
                nx[rr * 49 + c] = val;
            }
            __syncthreads();
        }

        bool okl = true;
        #pragma unroll
        for (int s = 0; s < 2; s++) {
            int e = tid + s * 256;
            int o = e >> 5, i = e & 31;
            float kv = augA[o * 49 + 16 + i];
            g_W[t][(SD + o) * SD + i] = kv;
            float pv = KPrev[e];
            KPrev[e] = kv;
            if (fabsf(kv - pv) >= 3e-6f) okl = false;
        }

        {
            const int i = lane, jg = wid;
            float w0 = FT[jg * P32 + i];
            float w1 = FT[(jg + 8) * P32 + i];
            float w2 = FT[(jg + 16) * P32 + i];
            float w3 = FT[(jg + 24) * P32 + i];
            #pragma unroll
            for (int o = 0; o < OD; o++) {
                float kv = augA[o * 49 + 16 + i];
                w0 -= Greg[o * 4 + 0] * kv;
                w1 -= Greg[o * 4 + 1] * kv;
                w2 -= Greg[o * 4 + 2] * kv;
                w3 -= Greg[o * 4 + 3] * kv;
            }
            float* wt = g_W[t];
            wt[jg * SD + i]        = w0;
            wt[(jg + 8) * SD + i]  = w1;
            wt[(jg + 16) * SD + i] = w2;
            wt[(jg + 24) * SD + i] = w3;
        }

        {
            const int j = lane, ig = wid;
            float p0 = Pp[ig * P32 + j];
            float p1 = Pp[(ig + 8) * P32 + j];
            float p2 = Pp[(ig + 16) * P32 + j];
            float p3 = Pp[(ig + 24) * P32 + j];
            #pragma unroll
            for (int o = 0; o < OD; o++) {
                float hv = HPs[o * P32 + j];
                p0 -= augA[o * 49 + 16 + ig] * hv;
                p1 -= augA[o * 49 + 16 + ig + 8] * hv;
                p2 -= augA[o * 49 + 16 + ig + 16] * hv;
                p3 -= augA[o * 49 + 16 + ig + 24] * hv;
            }
            Ps[ig * P32 + j]        = p0;
            Ps[(ig + 8) * P32 + j]  = p1;
            Ps[(ig + 16) * P32 + j] = p2;
            Ps[(ig + 24) * P32 + j] = p3;
        }

        int conv = __syncthreads_and((int)(okl && (t > 0)));
        if (conv) {
            if (tid == 0) g_tconv = t;
            break;
        }
    }
}

// ---------------------------------------------------------------------------
// FALLBACK phase 2 (verified R6 path) — no-op if g_special (set by phase1).
// ---------------------------------------------------------------------------
__global__ void __launch_bounds__(256, 1) phase2_kernel(
    const float* __restrict__ x0g,
    const float* __restrict__ meas,
    float* __restrict__ out)
{
    if (g_special) return;

    __shared__ float Wb[2][48 * SD];
    __shared__ float xs[8][2][SD + 1];
    __shared__ float zs[8][2][OD];

    const int tid  = threadIdx.x;
    const int bl   = tid >> 5;
    const int lane = tid & 31;
    const int b0   = (blockIdx.x * 8 + bl) * 2;
    const int b1   = b0 + 1;
    const int lzb  = (lane < OD) ? b0 : b1;
    const int lz   = lane & 15;
    const int tconv = g_tconv;

    xs[bl][0][lane] = x0g[b0 * SD + lane];
    xs[bl][1][lane] = x0g[b1 * SD + lane];
    zs[bl][lane >> 4][lz] = meas[(lzb * TT + 0) * OD + lz];
    {
        const float4* gw = (const float4*)g_W[0];
        float4* d = (float4*)Wb[0];
        d[tid] = gw[tid];
        if (tid < 128) d[256 + tid] = gw[256 + tid];
    }
    __syncthreads();

    int cur = 0;
    int tW = 0;

    #pragma unroll 1
    for (int t = 0; t < TT; t++) {
        int tn = (t + 1 < TT) ? ((t + 1 < tconv) ? (t + 1) : tconv) : tW;
        const bool stage = (tn != tW);

        float4 n0, n1;
        float zn;
        if (stage) {
            const float4* gw = (const float4*)g_W[tn];
            n0 = gw[tid];
            if (tid < 128) n1 = gw[256 + tid];
        }
        if (t + 1 < TT) zn = meas[(lzb * TT + (t + 1)) * OD + lz];

        const float* AT = Wb[cur];
        const float* KT = Wb[cur] + SD * SD;
        float a0 = 0.f, a1 = 0.f, c0 = 0.f, c1 = 0.f;
        #pragma unroll
        for (int j = 0; j < SD; j += 2) {
            float w0 = AT[j * SD + lane];
            float w1 = AT[(j + 1) * SD + lane];
            a0 += w0 * xs[bl][0][j];
            c0 += w0 * xs[bl][1][j];
            a1 += w1 * xs[bl][0][j + 1];
            c1 += w1 * xs[bl][1][j + 1];
        }
        #pragma unroll
        for (int o = 0; o < OD; o += 2) {
            float w0 = KT[o * SD + lane];
            float w1 = KT[(o + 1) * SD + lane];
            a0 += w0 * zs[bl][0][o];
            c0 += w0 * zs[bl][1][o];
            a1 += w1 * zs[bl][0][o + 1];
            c1 += w1 * zs[bl][1][o + 1];
        }
        const float xa = a0 + a1;
        const float xc = c0 + c1;
        out[(b0 * TT + t) * SD + lane] = xa;
        out[(b1 * TT + t) * SD + lane] = xc;
        __syncthreads();

        xs[bl][0][lane] = xa;
        xs[bl][1][lane] = xc;
        if (t + 1 < TT) zs[bl][lane >> 4][lz] = zn;
        if (stage) {
            float4* d = (float4*)Wb[cur ^ 1];
            d[tid] = n0;
            if (tid < 128) d[256 + tid] = n1;
            cur ^= 1;
            tW = tn;
        }
        __syncthreads();
    }
}

// ---------------------------------------------------------------------------
extern "C" void kernel_launch(void* const* d_in, const int* in_sizes, int n_in,
                              void* d_out, int out_size) {
    const float* state0 = (const float*)d_in[0];  // (B, 32)
    const float* cov0   = (const float*)d_in[1];  // (B, 32, 32)
    const float* meas   = (const float*)d_in[2];  // (B, 64, 16)
    const float* F      = (const float*)d_in[3];  // (32, 32)
    const float* H      = (const float*)d_in[4];  // (16, 32)
    const float* Q      = (const float*)d_in[5];  // (32, 32)
    const float* R      = (const float*)d_in[6];  // (16, 16)
    float* out = (float*)d_out;                   // (B, 64, 32)
    (void)in_sizes; (void)n_in; (void)out_size;

    const int dyn = 16 * TT * OD * (int)sizeof(float);   // 64 KB zb
    cudaFuncSetAttribute(fused_kernel,
                         cudaFuncAttributeMaxDynamicSharedMemorySize, dyn);

    fused_kernel<<<NB / 16, 512, dyn>>>(state0, meas, out, F, H, Q, R, cov0);
    phase1_kernel<<<1, 256>>>(F, H, Q, R, cov0);        // no-op if special
    phase2_kernel<<<NB / 16, 256>>>(state0, meas, out); // no-op if special
}

// round 11
// speedup vs baseline: 7.4743x; 1.0087x over previous
#include <cuda_runtime.h>
#include <math.h>

// Kalman filter B=2048, T=64, STATE=32, OBS=16.
// SPECIAL PATH (F=I, Q=qI, R=rI, cov0=I — verified per CTA):
//   fused_kernel: per-CTA Gram-matrix two-sided Jacobi eigendecomp of HH^T +
//   scalar gain recursions, then 16 warps each filter one batch.
// FALLBACK: verified phase1/phase2 (phase1 publishes g_special).

#define SD 32
#define OD 16
#define TT 64
#define NB 2048
#define P32 33
#define P16 17

__device__ int g_special;
__device__ __align__(16) float g_W[TT][48 * SD];
__device__ int g_tconv;

// ---------------------------------------------------------------------------
// Fused special-path kernel
// ---------------------------------------------------------------------------
__global__ void __launch_bounds__(512, 1) fused_kernel(
    const float* __restrict__ x0g,
    const float* __restrict__ meas,   // (B, T, 16)
    float* __restrict__ out,          // (B, T, 32)
    const float* __restrict__ Fg, const float* __restrict__ Hg,
    const float* __restrict__ Qg, const float* __restrict__ Rg,
    const float* __restrict__ cov0)
{
    extern __shared__ float4 zb_dyn[];      // [16][256] float4 = 64KB

    __shared__ float Hs[OD * 33];           // H rows (kept for V recovery)
    __shared__ float Ms[OD * 17];           // Gram matrix H H^T (symmetric)
    __shared__ float Wacc[OD * 17];         // accumulated rotations = U^T
    __shared__ float sig[OD];
    __shared__ float2 ab2[TT * OD];         // (a_i,t , k_i,t)
    __shared__ float Us[OD * OD];
    __shared__ float Vs[SD * 17];
    __shared__ int notconv;

    const int tid  = threadIdx.x;
    const int w    = tid >> 5;
    const int lane = tid & 31;
    const int i16  = lane & 15;
    const float q = Qg[0], r = Rg[0];

    // ---- issue batch loads EARLY (latency hidden behind Jacobi) ----
    const int b = blockIdx.x * 16 + w;
    const float4* zg = (const float4*)(meas + (size_t)b * TT * OD);
    float4 zr0 = zg[0 * 32 + lane];
    float4 zr1 = zg[1 * 32 + lane];
    float4 zr2 = zg[2 * 32 + lane];
    float4 zr3 = zg[3 * 32 + lane];
    float4 zr4 = zg[4 * 32 + lane];
    float4 zr5 = zg[5 * 32 + lane];
    float4 zr6 = zg[6 * 32 + lane];
    float4 zr7 = zg[7 * 32 + lane];
    float x0reg = x0g[b * SD + lane];

    // ---- specialness check (all 512 threads) ----
    {
        bool ok = (r > 0.f) && (q >= 0.f);
        #pragma unroll
        for (int s = 0; s < 2; s++) {
            int e = tid + s * 512;
            int i = e >> 5, j = e & 31;
            float ide = (i == j) ? 1.f : 0.f;
            if (Fg[e] != ide) ok = false;
            if (cov0[e] != ide) ok = false;
            if (Qg[e] != ((i == j) ? q : 0.f)) ok = false;
        }
        if (tid < 256) {
            int i = tid >> 4, j = tid & 15;
            if (Rg[tid] != ((i == j) ? r : 0.f)) ok = false;
        }
        int special = __syncthreads_and((int)ok);
        if (!special) return;    // fallback kernels handle it
    }

    // ---- load H to smem; init Wacc = I ----
    {
        int i = tid >> 5, j = tid & 31;
        Hs[i * 33 + j] = Hg[tid];
    }
    if (tid < 256) {
        int i = tid >> 4, m = tid & 15;
        Wacc[i * 17 + m] = (i == m) ? 1.f : 0.f;
    }
    __syncthreads();

    // ---- Gram matrix M = H H^T (256 entries, threads 0..255) ----
    if (tid < 256) {
        int rr = tid >> 4, cc = tid & 15;
        float acc0 = 0.f, acc1 = 0.f;
        #pragma unroll
        for (int k = 0; k < SD; k += 2) {
            acc0 += Hs[rr * 33 + k] * Hs[cc * 33 + k];
            acc1 += Hs[rr * 33 + k + 1] * Hs[cc * 33 + k + 1];
        }
        Ms[rr * 17 + cc] = acc0 + acc1;
    }
    __syncthreads();

    // ---- two-sided Jacobi on M (warps 0..7), adaptive sweeps ----
    for (int sweep = 0; sweep < 10; sweep++) {
        if (tid == 0) notconv = 0;
        __syncthreads();
        for (int rr = 0; rr < 15; rr++) {
            float c = 1.f, s = 0.f;
            bool rot = false;
            int p = 0, qq = 0;
            if (w < 8) {
                if (w == 0) { p = 0; qq = 1 + rr; }
                else { p = 1 + ((rr + w) % 15); qq = 1 + ((rr + 15 - w) % 15); }
                float mpp = Ms[p * 17 + p];
                float mqq = Ms[qq * 17 + qq];
                float mpq = Ms[p * 17 + qq];
                float g2 = mpq * mpq;
                rot = (g2 > 1e-16f * mpp * mqq);
                if (rot) {
                    float tau = (mqq - mpp) / (2.f * mpq);
                    float tt = ((tau >= 0.f) ? 1.f : -1.f) / (fabsf(tau) + sqrtf(1.f + tau * tau));
                    c = rsqrtf(1.f + tt * tt);
                    s = c * tt;
                }
                if (lane == 0 && (g2 > 1e-14f * mpp * mqq)) notconv = 1;
                // row phase: M rows p,q  (N = G M), Wacc rows p,q
                if (rot && lane < 16) {
                    float mp = Ms[p * 17 + lane], mq = Ms[qq * 17 + lane];
                    Ms[p * 17 + lane]  = c * mp - s * mq;
                    Ms[qq * 17 + lane] = s * mp + c * mq;
                    float up = Wacc[p * 17 + lane], uq = Wacc[qq * 17 + lane];
                    Wacc[p * 17 + lane]  = c * up - s * uq;
                    Wacc[qq * 17 + lane] = s * up + c * uq;
                }
            }
            __syncthreads();
            // col phase: M cols p,q  (M' = N G^T)
            if (w < 8 && rot && lane < 16) {
                float vp = Ms[lane * 17 + p], vq = Ms[lane * 17 + qq];
                Ms[lane * 17 + p]  = c * vp - s * vq;
                Ms[lane * 17 + qq] = s * vp + c * vq;
            }
            __syncthreads();
        }
        if (!notconv) break;
        __syncthreads();
    }

    // ---- sigma, U^T, V ----
    if (tid < OD) sig[tid] = sqrtf(fmaxf(Ms[tid * 17 + tid], 0.f));
    if (tid < 256) Us[tid] = Wacc[(tid >> 4) * 17 + (tid & 15)];
    __syncthreads();
    {
        // V[j][i] = (Wacc H)[i][j] / sig_i
        int j = tid >> 4, i = tid & 15;
        float acc0 = 0.f, acc1 = 0.f;
        #pragma unroll
        for (int o = 0; o < OD; o += 2) {
            acc0 += Wacc[i * 17 + o] * Hs[o * 33 + j];
            acc1 += Wacc[i * 17 + o + 1] * Hs[(o + 1) * 33 + j];
        }
        float sg = sig[i];
        float rsg = (sg > 1e-20f) ? (1.f / sg) : 0.f;
        Vs[j * 17 + i] = (acc0 + acc1) * rsg;
    }

    // ---- scalar gain recursion (threads 0..15) ----
    if (tid < OD) {
        float sg = sig[tid];
        float lam = sg * sg;
        float p = 1.f;
        #pragma unroll 1
        for (int t = 0; t < TT; t++) {
            float pp = p + q;
            float dinv = 1.f / (lam * pp + r);
            float a = r * dinv;
            float kk = pp * sg * dinv;
            ab2[t * 16 + tid] = make_float2(a, kk);
            p = a * pp;
        }
    }
    __syncthreads();

    // ---- per-warp batch filter ----
    float Ureg[16], Vreg[16];
    #pragma unroll
    for (int m = 0; m < 16; m++) Ureg[m] = Us[i16 * 16 + m];
    #pragma unroll
    for (int m = 0; m < 16; m++) Vreg[m] = Vs[lane * 17 + m];

    float4* zw = zb_dyn + w * (TT * OD / 4);

    // stash z tile (registers held through Jacobi -> DRAM latency hidden)
    zw[0 * 32 + lane] = zr0;  zw[1 * 32 + lane] = zr1;
    zw[2 * 32 + lane] = zr2;  zw[3 * 32 + lane] = zr3;
    zw[4 * 32 + lane] = zr4;  zw[5 * 32 + lane] = zr5;
    zw[6 * 32 + lane] = zr6;  zw[7 * 32 + lane] = zr7;
    __syncwarp();

    // w[t] = U^T z[t], in place; ILP-4 partial accumulators
    #pragma unroll 4
    for (int it = 0; it < 32; it++) {
        const int t = it * 2 + (lane >> 4);
        float4 z0 = zw[t * 4 + 0];
        float4 z1 = zw[t * 4 + 1];
        float4 z2 = zw[t * 4 + 2];
        float4 z3 = zw[t * 4 + 3];
        float p0 = Ureg[0] * z0.x + Ureg[1] * z0.y + Ureg[2] * z0.z + Ureg[3] * z0.w;
        float p1 = Ureg[4] * z1.x + Ureg[5] * z1.y + Ureg[6] * z1.z + Ureg[7] * z1.w;
        float p2 = Ureg[8] * z2.x + Ureg[9] * z2.y + Ureg[10] * z2.z + Ureg[11] * z2.w;
        float p3 = Ureg[12] * z3.x + Ureg[13] * z3.y + Ureg[14] * z3.z + Ureg[15] * z3.w;
        float acc = (p0 + p1) + (p2 + p3);
        __syncwarp();
        ((float*)zw)[t * 16 + i16] = acc;
    }
    __syncwarp();

    // y0 = V^T x0 (component i16, duplicated across half-warps)
    float y = 0.f;
    #pragma unroll
    for (int j = 0; j < 32; j++)
        y += Vs[j * 17 + i16] * __shfl_sync(0xffffffffu, x0reg, j);

    // u[j] = x0[j] - sum_i V[j][i] y0_i
    float u = x0reg;
    #pragma unroll
    for (int m = 0; m < 16; m++)
        u -= Vreg[m] * __shfl_sync(0xffffffffu, y, m);

    // scalar scans: y_t = a y + k w (lanes 0..15), overwrite w with y
    if (lane < 16) {
        float* yw = (float*)zw;
        #pragma unroll 1
        for (int t = 0; t < TT; t++) {
            float2 akv = ab2[t * 16 + i16];
            float wv = yw[t * 16 + i16];
            y = akv.x * y + akv.y * wv;
            yw[t * 16 + i16] = y;
        }
    }
    __syncwarp();

    // out[t][j] = u[j] + sum_i V[j][i] y[t][i]; ILP-4 partials
    float* ob = out + (size_t)b * TT * SD;
    #pragma unroll 2
    for (int t = 0; t < TT; t++) {
        float4 y0 = zw[t * 4 + 0];
        float4 y1 = zw[t * 4 + 1];
        float4 y2 = zw[t * 4 + 2];
        float4 y3 = zw[t * 4 + 3];
        float p0 = Vreg[0] * y0.x + Vreg[1] * y0.y + Vreg[2] * y0.z + Vreg[3] * y0.w;
        float p1 = Vreg[4] * y1.x + Vreg[5] * y1.y + Vreg[6] * y1.z + Vreg[7] * y1.w;
        float p2 = Vreg[8] * y2.x + Vreg[9] * y2.y + Vreg[10] * y2.z + Vreg[11] * y2.w;
        float p3 = Vreg[12] * y3.x + Vreg[13] * y3.y + Vreg[14] * y3.z + Vreg[15] * y3.w;
        ob[t * SD + lane] = ((u + p0) + p1) + (p2 + p3);
    }
}

// ---------------------------------------------------------------------------
// FALLBACK phase 1 (verified) — performs specialness check, publishes g_special.
// ---------------------------------------------------------------------------
__global__ void __launch_bounds__(256, 1) phase1_kernel(
    const float* __restrict__ Fg, const float* __restrict__ Hg,
    const float* __restrict__ Qg, const float* __restrict__ Rg,
    const float* __restrict__ cov0)
{
    __shared__ float Fs[SD * P32];
    __shared__ float FT[SD * P32];
    __shared__ float Qs[SD * P32];
    __shared__ float Hs[OD * P32];
    __shared__ float Rs[OD * P16];
    __shared__ float Gs[OD * P32];
    __shared__ float Ps[SD * P32];
    __shared__ float Pp[SD * P32];
    __shared__ float T1[SD * P32];
    __shared__ float HPs[OD * P32];
    __shared__ float augA[OD * 49];
    __shared__ float augB[OD * 49];
    __shared__ float KPrev[OD * SD];
    __shared__ int fid;

    const int tid  = threadIdx.x;
    const int wid  = tid >> 5;
    const int lane = tid & 31;
    const int half = lane >> 4;
    const int rsel = wid + 8 * half;

    if (tid == 0) { fid = 1; g_tconv = TT - 1; }
    __syncthreads();

    const float q = Qg[0], r = Rg[0];
    {
        bool okF = true;
        bool okSp = (r > 0.f) && (q >= 0.f);
        #pragma unroll
        for (int s = 0; s < 4; s++) {
            int e = tid + s * 256;
            int i = e >> 5, j = e & 31;
            float ide = (i == j) ? 1.0f : 0.0f;
            float f = Fg[e];
            Fs[i * P32 + j] = f;
            FT[j * P32 + i] = f;
            Qs[i * P32 + j] = Qg[e];
            Ps[i * P32 + j] = cov0[e];
            if (f != ide) okF = false;
            if (Qg[e] != ((i == j) ? q : 0.f)) okSp = false;
            if (cov0[e] != ide) okSp = false;
        }
        if (!okF) fid = 0;
        #pragma unroll
        for (int s = 0; s < 2; s++) {
            int e = tid + s * 256;
            Hs[(e >> 5) * P32 + (e & 31)] = Hg[e];
        }
        Rs[(tid >> 4) * P16 + (tid & 15)] = Rg[tid];
        {
            int i = tid >> 4, j = tid & 15;
            if (Rg[tid] != ((i == j) ? r : 0.f)) okSp = false;
        }
        int special = __syncthreads_and((int)(okF && okSp));
        if (tid == 0) g_special = special;
        if (special) return;
    }
    __syncthreads();

    float hsel[SD];
    #pragma unroll
    for (int k = 0; k < SD; k++) hsel[k] = Hs[rsel * P32 + k];

    #pragma unroll
    for (int s = 0; s < 2; s++) {
        int e = tid + s * 256;
        int o = e >> 5, j = e & 31;
        float acc = 0.f;
        #pragma unroll
        for (int k = 0; k < SD; k++) acc += Hs[o * P32 + k] * FT[j * P32 + k];
        Gs[o * P32 + j] = acc;
    }
    const int ident = fid;
    __syncthreads();

    float Greg[OD * 4];
    #pragma unroll
    for (int o = 0; o < OD; o++) {
        Greg[o * 4 + 0] = Gs[o * P32 + wid];
        Greg[o * 4 + 1] = Gs[o * P32 + wid + 8];
        Greg[o * 4 + 2] = Gs[o * P32 + wid + 16];
        Greg[o * 4 + 3] = Gs[o * P32 + wid + 24];
    }

    #pragma unroll 1
    for (int t = 0; t < TT; t++) {
        if (ident) {
            #pragma unroll
            for (int s = 0; s < 4; s++) {
                int e = tid + s * 256;
                int idx = (e >> 5) * P32 + (e & 31);
                Pp[idx] = Ps[idx] + Qs[idx];
            }
        } else {
            #pragma unroll
            for (int s = 0; s < 4; s++) {
                int e = tid + s * 256;
                int i = e >> 5, j = e & 31;
                float acc = 0.f;
                #pragma unroll
                for (int k = 0; k < SD; k++) acc += Fs[i * P32 + k] * Ps[k * P32 + j];
                T1[i * P32 + j] = acc;
            }
            __syncthreads();
            #pragma unroll
            for (int s = 0; s < 4; s++) {
                int e = tid + s * 256;
                int i = e >> 5, j = e & 31;
                float acc = Qs[i * P32 + j];
                #pragma unroll
                for (int k = 0; k < SD; k++) acc += T1[i * P32 + k] * Fs[j * P32 + k];
                Pp[i * P32 + j] = acc;
            }
        }
        __syncthreads();

        {
            const int j0 = lane & 15;
            float a0 = 0.f, a1 = 0.f;
            #pragma unroll
            for (int k = 0; k < SD; k++) {
                float p0 = Pp[k * P32 + j0];
                float p1 = Pp[k * P32 + j0 + 16];
                a0 += hsel[k] * p0;
                a1 += hsel[k] * p1;
            }
            HPs[rsel * P32 + j0]      = a0;
            HPs[rsel * P32 + j0 + 16] = a1;
        }
        __syncthreads();

        {
            const int rr = lane & 15;
            float acc = Rs[rr * P16 + rsel];
            #pragma unroll
            for (int k = 0; k < SD; k++) acc += HPs[rr * P32 + k] * hsel[k];
            augA[rr * 49 + rsel] = acc;
        }
        #pragma unroll
        for (int s = 0; s < 2; s++) {
            int e = tid + s * 256;
            int rr = e >> 5, i = e & 31;
            augA[rr * 49 + 16 + i] = HPs[rr * P32 + i];
        }
        __syncthreads();

        #pragma unroll 1
        for (int rd = 0; rd < 8; rd++) {
            const float* cu = (rd & 1) ? augB : augA;
            float* nx = (rd & 1) ? augA : augB;
            const int p = 2 * rd;
            const float a  = cu[p * 49 + p];
            const float bb = cu[p * 49 + p + 1];
            const float cc = cu[(p + 1) * 49 + p];
            const float dd = cu[(p + 1) * 49 + p + 1];
            const float rdet = 1.0f / (a * dd - bb * cc);
            const int aw = 46 - 2 * rd;
            const int cb = p + 2;
            const int tot = OD * aw;
            for (int e = tid; e < tot; e += 256) {
                int rr = e / aw;
                int c = cb + (e - rr * aw);
                float rp = cu[p * 49 + c];
                float rq = cu[(p + 1) * 49 + c];
                float np = (dd * rp - bb * rq) * rdet;
                float nq = (a * rq - cc * rp) * rdet;
                float val;
                if (rr == p)          val = np;
                else if (rr == p + 1) val = nq;
                else                  val = cu[rr * 49 + c] - cu[rr * 49 + p] * np - cu[rr * 49 + p + 1] * nq;
                nx[rr * 49 + c] = val;
            }
            __syncthreads();
        }

        bool okl = true;
        #pragma unroll
        for (int s = 0; s < 2; s++) {
            int e = tid + s * 256;
            int o = e >> 5, i = e & 31;
            float kv = augA[o * 49 + 16 + i];
            g_W[t][(SD + o) * SD + i] = kv;
            float pv = KPrev[e];
            KPrev[e] = kv;
            if (fabsf(kv - pv) >= 3e-6f) okl = false;
        }

        {
            const int i = lane, jg = wid;
            float w0 = FT[jg * P32 + i];
            float w1 = FT[(jg + 8) * P32 + i];
            float w2 = FT[(jg + 16) * P32 + i];
            float w3 = FT[(jg + 24) * P32 + i];
            #pragma unroll
            for (int o = 0; o < OD; o++) {
                float kv = augA[o * 49 + 16 + i];
                w0 -= Greg[o * 4 + 0] * kv;
                w1 -= Greg[o * 4 + 1] * kv;
                w2 -= Greg[o * 4 + 2] * kv;
                w3 -= Greg[o * 4 + 3] * kv;
            }
            float* wt = g_W[t];
            wt[jg * SD + i]        = w0;
            wt[(jg + 8) * SD + i]  = w1;
            wt[(jg + 16) * SD + i] = w2;
            wt[(jg + 24) * SD + i] = w3;
        }

        {
            const int j = lane, ig = wid;
            float p0 = Pp[ig * P32 + j];
            float p1 = Pp[(ig + 8) * P32 + j];
            float p2 = Pp[(ig + 16) * P32 + j];
            float p3 = Pp[(ig + 24) * P32 + j];
            #pragma unroll
            for (int o = 0; o < OD; o++) {
                float hv = HPs[o * P32 + j];
                p0 -= augA[o * 49 + 16 + ig] * hv;
                p1 -= augA[o * 49 + 16 + ig + 8] * hv;
                p2 -= augA[o * 49 + 16 + ig + 16] * hv;
                p3 -= augA[o * 49 + 16 + ig + 24] * hv;
            }
            Ps[ig * P32 + j]        = p0;
            Ps[(ig + 8) * P32 + j]  = p1;
            Ps[(ig + 16) * P32 + j] = p2;
            Ps[(ig + 24) * P32 + j] = p3;
        }

        int conv = __syncthreads_and((int)(okl && (t > 0)));
        if (conv) {
            if (tid == 0) g_tconv = t;
            break;
        }
    }
}

// ---------------------------------------------------------------------------
// FALLBACK phase 2 (verified) — no-op if g_special.
// ---------------------------------------------------------------------------
__global__ void __launch_bounds__(256, 1) phase2_kernel(
    const float* __restrict__ x0g,
    const float* __restrict__ meas,
    float* __restrict__ out)
{
    if (g_special) return;

    __shared__ float Wb[2][48 * SD];
    __shared__ float xs[8][2][SD + 1];
    __shared__ float zs[8][2][OD];

    const int tid  = threadIdx.x;
    const int bl   = tid >> 5;
    const int lane = tid & 31;
    const int b0   = (blockIdx.x * 8 + bl) * 2;
    const int b1   = b0 + 1;
    const int lzb  = (lane < OD) ? b0 : b1;
    const int lz   = lane & 15;
    const int tconv = g_tconv;

    xs[bl][0][lane] = x0g[b0 * SD + lane];
    xs[bl][1][lane] = x0g[b1 * SD + lane];
    zs[bl][lane >> 4][lz] = meas[(lzb * TT + 0) * OD + lz];
    {
        const float4* gw = (const float4*)g_W[0];
        float4* d = (float4*)Wb[0];
        d[tid] = gw[tid];
        if (tid < 128) d[256 + tid] = gw[256 + tid];
    }
    __syncthreads();

    int cur = 0;
    int tW = 0;

    #pragma unroll 1
    for (int t = 0; t < TT; t++) {
        int tn = (t + 1 < TT) ? ((t + 1 < tconv) ? (t + 1) : tconv) : tW;
        const bool stage = (tn != tW);

        float4 n0, n1;
        float zn;
        if (stage) {
            const float4* gw = (const float4*)g_W[tn];
            n0 = gw[tid];
            if (tid < 128) n1 = gw[256 + tid];
        }
        if (t + 1 < TT) zn = meas[(lzb * TT + (t + 1)) * OD + lz];

        const float* AT = Wb[cur];
        const float* KT = Wb[cur] + SD * SD;
        float a0 = 0.f, a1 = 0.f, c0 = 0.f, c1 = 0.f;
        #pragma unroll
        for (int j = 0; j < SD; j += 2) {
            float w0 = AT[j * SD + lane];
            float w1 = AT[(j + 1) * SD + lane];
            a0 += w0 * xs[bl][0][j];
            c0 += w0 * xs[bl][1][j];
            a1 += w1 * xs[bl][0][j + 1];
            c1 += w1 * xs[bl][1][j + 1];
        }
        #pragma unroll
        for (int o = 0; o < OD; o += 2) {
            float w0 = KT[o * SD + lane];
            float w1 = KT[(o + 1) * SD + lane];
            a0 += w0 * zs[bl][0][o];
            c0 += w0 * zs[bl][1][o];
            a1 += w1 * zs[bl][0][o + 1];
            c1 += w1 * zs[bl][1][o + 1];
        }
        const float xa = a0 + a1;
        const float xc = c0 + c1;
        out[(b0 * TT + t) * SD + lane] = xa;
        out[(b1 * TT + t) * SD + lane] = xc;
        __syncthreads();

        xs[bl][0][lane] = xa;
        xs[bl][1][lane] = xc;
        if (t + 1 < TT) zs[bl][lane >> 4][lz] = zn;
        if (stage) {
            float4* d = (float4*)Wb[cur ^ 1];
            d[tid] = n0;
            if (tid < 128) d[256 + tid] = n1;
            cur ^= 1;
            tW = tn;
        }
        __syncthreads();
    }
}

// ---------------------------------------------------------------------------
extern "C" void kernel_launch(void* const* d_in, const int* in_sizes, int n_in,
                              void* d_out, int out_size) {
    const float* state0 = (const float*)d_in[0];  // (B, 32)
    const float* cov0   = (const float*)d_in[1];  // (B, 32, 32)
    const float* meas   = (const float*)d_in[2];  // (B, 64, 16)
    const float* F      = (const float*)d_in[3];  // (32, 32)
    const float* H      = (const float*)d_in[4];  // (16, 32)
    const float* Q      = (const float*)d_in[5];  // (32, 32)
    const float* R      = (const float*)d_in[6];  // (16, 16)
    float* out = (float*)d_out;                   // (B, 64, 32)
    (void)in_sizes; (void)n_in; (void)out_size;

    const int dyn = 16 * TT * OD * (int)sizeof(float);   // 64 KB zb
    cudaFuncSetAttribute(fused_kernel,
                         cudaFuncAttributeMaxDynamicSharedMemorySize, dyn);

    fused_kernel<<<NB / 16, 512, dyn>>>(state0, meas, out, F, H, Q, R, cov0);
    phase1_kernel<<<1, 256>>>(F, H, Q, R, cov0);        // no-op if special
    phase2_kernel<<<NB / 16, 256>>>(state0, meas, out); // no-op if special
}

// round 12
// speedup vs baseline: 8.8610x; 1.1855x over previous
#include <cuda_runtime.h>
#include <math.h>

// Kalman filter B=2048, T=64, STATE=32, OBS=16.
// SPECIAL PATH (F=I, Q=qI, R=rI, cov0=I — verified per CTA):
//   fused_kernel: per-CTA Gram-matrix Jacobi eigendecomp of HH^T (noise-level
//   early exit, narrow named barrier) + scalar gain recursions, then 16 warps
//   each filter one batch.
// FALLBACK: verified phase1/phase2 (phase1 publishes g_special).

#define SD 32
#define OD 16
#define TT 64
#define NB 2048
#define P32 33
#define P16 17

#define BAR1() asm volatile("bar.sync 1, 256;" ::: "memory")

__device__ int g_special;
__device__ __align__(16) float g_W[TT][48 * SD];
__device__ int g_tconv;

// ---------------------------------------------------------------------------
// Fused special-path kernel
// ---------------------------------------------------------------------------
__global__ void __launch_bounds__(512, 1) fused_kernel(
    const float* __restrict__ x0g,
    const float* __restrict__ meas,   // (B, T, 16)
    float* __restrict__ out,          // (B, T, 32)
    const float* __restrict__ Fg, const float* __restrict__ Hg,
    const float* __restrict__ Qg, const float* __restrict__ Rg,
    const float* __restrict__ cov0)
{
    extern __shared__ float4 zb_dyn[];      // [16][256] float4 = 64KB

    __shared__ float Hs[OD * 33];           // H rows (kept for V recovery)
    __shared__ float Ms[OD * 17];           // Gram matrix H H^T
    __shared__ float Wacc[OD * 17];         // accumulated rotations = U^T
    __shared__ float sig[OD];
    __shared__ float2 ab2[TT * OD];         // (a_i,t , k_i,t)
    __shared__ float Us[OD * OD];
    __shared__ float Vs[SD * 17];
    __shared__ float thr2s;
    __shared__ int notconv;

    const int tid  = threadIdx.x;
    const int w    = tid >> 5;
    const int lane = tid & 31;
    const int i16  = lane & 15;
    const float q = Qg[0], r = Rg[0];

    // ---- issue batch loads EARLY ----
    const int b = blockIdx.x * 16 + w;
    const float4* zg = (const float4*)(meas + (size_t)b * TT * OD);
    float4 zr0 = zg[0 * 32 + lane];
    float4 zr1 = zg[1 * 32 + lane];
    float4 zr2 = zg[2 * 32 + lane];
    float4 zr3 = zg[3 * 32 + lane];
    float4 zr4 = zg[4 * 32 + lane];
    float4 zr5 = zg[5 * 32 + lane];
    float4 zr6 = zg[6 * 32 + lane];
    float4 zr7 = zg[7 * 32 + lane];
    float x0reg = x0g[b * SD + lane];

    // ---- specialness check (all 512 threads) ----
    {
        bool ok = (r > 0.f) && (q >= 0.f);
        #pragma unroll
        for (int s = 0; s < 2; s++) {
            int e = tid + s * 512;
            int i = e >> 5, j = e & 31;
            float ide = (i == j) ? 1.f : 0.f;
            if (Fg[e] != ide) ok = false;
            if (cov0[e] != ide) ok = false;
            if (Qg[e] != ((i == j) ? q : 0.f)) ok = false;
        }
        if (tid < 256) {
            int i = tid >> 4, j = tid & 15;
            if (Rg[tid] != ((i == j) ? r : 0.f)) ok = false;
        }
        int special = __syncthreads_and((int)ok);
        if (!special) return;    // fallback kernels handle it
    }

    // ---- stash z tile to smem (frees registers through Jacobi) ----
    float4* zw = zb_dyn + w * (TT * OD / 4);
    zw[0 * 32 + lane] = zr0;  zw[1 * 32 + lane] = zr1;
    zw[2 * 32 + lane] = zr2;  zw[3 * 32 + lane] = zr3;
    zw[4 * 32 + lane] = zr4;  zw[5 * 32 + lane] = zr5;
    zw[6 * 32 + lane] = zr6;  zw[7 * 32 + lane] = zr7;

    // ---- load H to smem; init Wacc = I ----
    {
        int i = tid >> 5, j = tid & 31;
        Hs[i * 33 + j] = Hg[tid];
    }
    if (tid < 256) {
        int i = tid >> 4, m = tid & 15;
        Wacc[i * 17 + m] = (i == m) ? 1.f : 0.f;
    }
    __syncthreads();

    // ---- Gram matrix M = H H^T ----
    if (tid < 256) {
        int rr = tid >> 4, cc = tid & 15;
        float acc0 = 0.f, acc1 = 0.f;
        #pragma unroll
        for (int k = 0; k < SD; k += 2) {
            acc0 += Hs[rr * 33 + k] * Hs[cc * 33 + k];
            acc1 += Hs[rr * 33 + k + 1] * Hs[cc * 33 + k + 1];
        }
        Ms[rr * 17 + cc] = acc0 + acc1;
    }
    __syncthreads();

    // ---- global noise threshold: (1e-6 * mean eigenvalue)^2 ----
    if (tid == 0) {
        float tr = 0.f;
        #pragma unroll
        for (int i = 0; i < OD; i++) tr += Ms[i * 17 + i];
        float th = tr * (1e-6f / 16.f);
        thr2s = th * th;
        notconv = 0;
    }
    __syncthreads();

    // ---- two-sided Jacobi on M: warps 0..7, named barrier (256 threads) ----
    if (w < 8) {
        const float thr2 = thr2s;
        int cont = 1;
        for (int sweep = 0; sweep < 7 && cont; sweep++) {
            if (tid == 0) notconv = 0;
            BAR1();
            for (int rr = 0; rr < 15; rr++) {
                float c = 1.f, s = 0.f;
                bool rot;
                int p, qq;
                if (w == 0) { p = 0; qq = 1 + rr; }
                else { p = 1 + ((rr + w) % 15); qq = 1 + ((rr + 15 - w) % 15); }
                float mpp = Ms[p * 17 + p];
                float mqq = Ms[qq * 17 + qq];
                float mpq = Ms[p * 17 + qq];
                float g2 = mpq * mpq;
                rot = (g2 > thr2);
                if (rot) {
                    float tau = (mqq - mpp) / (2.f * mpq);
                    float tt = ((tau >= 0.f) ? 1.f : -1.f) / (fabsf(tau) + sqrtf(1.f + tau * tau));
                    c = rsqrtf(1.f + tt * tt);
                    s = c * tt;
                }
                if (lane == 0 && rot) notconv = 1;
                // row phase: M rows p,q  (N = G M), Wacc rows p,q
                if (rot && lane < 16) {
                    float mp = Ms[p * 17 + lane], mq = Ms[qq * 17 + lane];
                    Ms[p * 17 + lane]  = c * mp - s * mq;
                    Ms[qq * 17 + lane] = s * mp + c * mq;
                    float up = Wacc[p * 17 + lane], uq = Wacc[qq * 17 + lane];
                    Wacc[p * 17 + lane]  = c * up - s * uq;
                    Wacc[qq * 17 + lane] = s * up + c * uq;
                }
                BAR1();
                // col phase: M cols p,q  (M' = N G^T)
                if (rot && lane < 16) {
                    float vp = Ms[lane * 17 + p], vq = Ms[lane * 17 + qq];
                    Ms[lane * 17 + p]  = c * vp - s * vq;
                    Ms[lane * 17 + qq] = s * vp + c * vq;
                }
                BAR1();
            }
            cont = notconv;
            BAR1();   // all reads of notconv done before next sweep's zero
        }
        // sigma, U^T copy (within warps 0..7; Ms/Wacc visible after BAR1)
        if (tid < OD) sig[tid] = sqrtf(fmaxf(Ms[tid * 17 + tid], 0.f));
        if (tid < 256) Us[tid] = Wacc[(tid >> 4) * 17 + (tid & 15)];
    }
    __syncthreads();   // warps 8..15 waited here; sig/Us/Wacc/Hs now visible

    {
        // V[j][i] = (Wacc H)[i][j] / sig_i   (all 512 threads)
        int j = tid >> 4, i = tid & 15;
        float acc0 = 0.f, acc1 = 0.f;
        #pragma unroll
        for (int o = 0; o < OD; o += 2) {
            acc0 += Wacc[i * 17 + o] * Hs[o * 33 + j];
            acc1 += Wacc[i * 17 + o + 1] * Hs[(o + 1) * 33 + j];
        }
        float sg = sig[i];
        float rsg = (sg > 1e-20f) ? (1.f / sg) : 0.f;
        Vs[j * 17 + i] = (acc0 + acc1) * rsg;
    }

    // ---- scalar gain recursion (threads 0..15) ----
    if (tid < OD) {
        float sg = sig[tid];
        float lam = sg * sg;
        float p = 1.f;
        #pragma unroll 1
        for (int t = 0; t < TT; t++) {
            float pp = p + q;
            float dinv = 1.f / (lam * pp + r);
            float a = r * dinv;
            float kk = pp * sg * dinv;
            ab2[t * 16 + tid] = make_float2(a, kk);
            p = a * pp;
        }
    }
    __syncthreads();

    // ---- per-warp batch filter ----
    float Ureg[16], Vreg[16];
    #pragma unroll
    for (int m = 0; m < 16; m++) Ureg[m] = Us[i16 * 16 + m];
    #pragma unroll
    for (int m = 0; m < 16; m++) Vreg[m] = Vs[lane * 17 + m];

    // w[t] = U^T z[t], in place; ILP-4 partial accumulators
    #pragma unroll 4
    for (int it = 0; it < 32; it++) {
        const int t = it * 2 + (lane >> 4);
        float4 z0 = zw[t * 4 + 0];
        float4 z1 = zw[t * 4 + 1];
        float4 z2 = zw[t * 4 + 2];
        float4 z3 = zw[t * 4 + 3];
        float p0 = Ureg[0] * z0.x + Ureg[1] * z0.y + Ureg[2] * z0.z + Ureg[3] * z0.w;
        float p1 = Ureg[4] * z1.x + Ureg[5] * z1.y + Ureg[6] * z1.z + Ureg[7] * z1.w;
        float p2 = Ureg[8] * z2.x + Ureg[9] * z2.y + Ureg[10] * z2.z + Ureg[11] * z2.w;
        float p3 = Ureg[12] * z3.x + Ureg[13] * z3.y + Ureg[14] * z3.z + Ureg[15] * z3.w;
        float acc = (p0 + p1) + (p2 + p3);
        __syncwarp();
        ((float*)zw)[t * 16 + i16] = acc;
    }
    __syncwarp();

    // y0 = V^T x0 (component i16, duplicated across half-warps)
    float y = 0.f;
    #pragma unroll
    for (int j = 0; j < 32; j++)
        y += Vs[j * 17 + i16] * __shfl_sync(0xffffffffu, x0reg, j);

    // u[j] = x0[j] - sum_i V[j][i] y0_i
    float u = x0reg;
    #pragma unroll
    for (int m = 0; m < 16; m++)
        u -= Vreg[m] * __shfl_sync(0xffffffffu, y, m);

    // scalar scans: y_t = a y + k w (lanes 0..15), overwrite w with y
    if (lane < 16) {
        float* yw = (float*)zw;
        #pragma unroll 1
        for (int t = 0; t < TT; t++) {
            float2 akv = ab2[t * 16 + i16];
            float wv = yw[t * 16 + i16];
            y = akv.x * y + akv.y * wv;
            yw[t * 16 + i16] = y;
        }
    }
    __syncwarp();

    // out[t][j] = u[j] + sum_i V[j][i] y[t][i]; ILP-4 partials
    float* ob = out + (size_t)b * TT * SD;
    #pragma unroll 2
    for (int t = 0; t < TT; t++) {
        float4 y0 = zw[t * 4 + 0];
        float4 y1 = zw[t * 4 + 1];
        float4 y2 = zw[t * 4 + 2];
        float4 y3 = zw[t * 4 + 3];
        float p0 = Vreg[0] * y0.x + Vreg[1] * y0.y + Vreg[2] * y0.z + Vreg[3] * y0.w;
        float p1 = Vreg[4] * y1.x + Vreg[5] * y1.y + Vreg[6] * y1.z + Vreg[7] * y1.w;
        float p2 = Vreg[8] * y2.x + Vreg[9] * y2.y + Vreg[10] * y2.z + Vreg[11] * y2.w;
        float p3 = Vreg[12] * y3.x + Vreg[13] * y3.y + Vreg[14] * y3.z + Vreg[15] * y3.w;
        ob[t * SD + lane] = ((u + p0) + p1) + (p2 + p3);
    }
}

// ---------------------------------------------------------------------------
// FALLBACK phase 1 (verified) — performs specialness check, publishes g_special.
// ---------------------------------------------------------------------------
__global__ void __launch_bounds__(256, 1) phase1_kernel(
    const float* __restrict__ Fg, const float* __restrict__ Hg,
    const float* __restrict__ Qg, const float* __restrict__ Rg,
    const float* __restrict__ cov0)
{
    __shared__ float Fs[SD * P32];
    __shared__ float FT[SD * P32];
    __shared__ float Qs[SD * P32];
    __shared__ float Hs[OD * P32];
    __shared__ float Rs[OD * P16];
    __shared__ float Gs[OD * P32];
    __shared__ float Ps[SD * P32];
    __shared__ float Pp[SD * P32];
    __shared__ float T1[SD * P32];
    __shared__ float HPs[OD * P32];
    __shared__ float augA[OD * 49];
    __shared__ float augB[OD * 49];
    __shared__ float KPrev[OD * SD];
    __shared__ int fid;

    const int tid  = threadIdx.x;
    const int wid  = tid >> 5;
    const int lane = tid & 31;
    const int half = lane >> 4;
    const int rsel = wid + 8 * half;

    if (tid == 0) { fid = 1; g_tconv = TT - 1; }
    __syncthreads();

    const float q = Qg[0], r = Rg[0];
    {
        bool okF = true;
        bool okSp = (r > 0.f) && (q >= 0.f);
        #pragma unroll
        for (int s = 0; s < 4; s++) {
            int e = tid + s * 256;
            int i = e >> 5, j = e & 31;
            float ide = (i == j) ? 1.0f : 0.0f;
            float f = Fg[e];
            Fs[i * P32 + j] = f;
            FT[j * P32 + i] = f;
            Qs[i * P32 + j] = Qg[e];
            Ps[i * P32 + j] = cov0[e];
            if (f != ide) okF = false;
            if (Qg[e] != ((i == j) ? q : 0.f)) okSp = false;
            if (cov0[e] != ide) okSp = false;
        }
        if (!okF) fid = 0;
        #pragma unroll
        for (int s = 0; s < 2; s++) {
            int e = tid + s * 256;
            Hs[(e >> 5) * P32 + (e & 31)] = Hg[e];
        }
        Rs[(tid >> 4) * P16 + (tid & 15)] = Rg[tid];
        {
            int i = tid >> 4, j = tid & 15;
            if (Rg[tid] != ((i == j) ? r : 0.f)) okSp = false;
        }
        int special = __syncthreads_and((int)(okF && okSp));
        if (tid == 0) g_special = special;
        if (special) return;
    }
    __syncthreads();

    float hsel[SD];
    #pragma unroll
    for (int k = 0; k < SD; k++) hsel[k] = Hs[rsel * P32 + k];

    #pragma unroll
    for (int s = 0; s < 2; s++) {
        int e = tid + s * 256;
        int o = e >> 5, j = e & 31;
        float acc = 0.f;
        #pragma unroll
        for (int k = 0; k < SD; k++) acc += Hs[o * P32 + k] * FT[j * P32 + k];
        Gs[o * P32 + j] = acc;
    }
    const int ident = fid;
    __syncthreads();

    float Greg[OD * 4];
    #pragma unroll
    for (int o = 0; o < OD; o++) {
        Greg[o * 4 + 0] = Gs[o * P32 + wid];
        Greg[o * 4 + 1] = Gs[o * P32 + wid + 8];
        Greg[o * 4 + 2] = Gs[o * P32 + wid + 16];
        Greg[o * 4 + 3] = Gs[o * P32 + wid + 24];
    }

    #pragma unroll 1
    for (int t = 0; t < TT; t++) {
        if (ident) {
            #pragma unroll
            for (int s = 0; s < 4; s++) {
                int e = tid + s * 256;
                int idx = (e >> 5) * P32 + (e & 31);
                Pp[idx] = Ps[idx] + Qs[idx];
            }
        } else {
            #pragma unroll
            for (int s = 0; s < 4; s++) {
                int e = tid + s * 256;
                int i = e >> 5, j = e & 31;
                float acc = 0.f;
                #pragma unroll
                for (int k = 0; k < SD; k++) acc += Fs[i * P32 + k] * Ps[k * P32 + j];
                T1[i * P32 + j] = acc;
            }
            __syncthreads();
            #pragma unroll
            for (int s = 0; s < 4; s++) {
                int e = tid + s * 256;
                int i = e >> 5, j = e & 31;
                float acc = Qs[i * P32 + j];
                #pragma unroll
                for (int k = 0; k < SD; k++) acc += T1[i * P32 + k] * Fs[j * P32 + k];
                Pp[i * P32 + j] = acc;
            }
        }
        __syncthreads();

        {
            const int j0 = lane & 15;
            float a0 = 0.f, a1 = 0.f;
            #pragma unroll
            for (int k = 0; k < SD; k++) {
                float p0 = Pp[k * P32 + j0];
                float p1 = Pp[k * P32 + j0 + 16];
                a0 += hsel[k] * p0;
                a1 += hsel[k] * p1;
            }
            HPs[rsel * P32 + j0]      = a0;
            HPs[rsel * P32 + j0 + 16] = a1;
        }
        __syncthreads();

        {
            const int rr = lane & 15;
            float acc = Rs[rr * P16 + rsel];
            #pragma unroll
            for (int k = 0; k < SD; k++) acc += HPs[rr * P32 + k] * hsel[k];
            augA[rr * 49 + rsel] = acc;
        }
        #pragma unroll
        for (int s = 0; s < 2; s++) {
            int e = tid + s * 256;
            int rr = e >> 5, i = e & 31;
            augA[rr * 49 + 16 + i] = HPs[rr * P32 + i];
        }
        __syncthreads();

        #pragma unroll 1
        for (int rd = 0; rd < 8; rd++) {
            const float* cu = (rd & 1) ? augB : augA;
            float* nx = (rd & 1) ? augA : augB;
            const int p = 2 * rd;
            const float a  = cu[p * 49 + p];
            const float bb = cu[p * 49 + p + 1];
            const float cc = cu[(p + 1) * 49 + p];
            const float dd = cu[(p + 1) * 49 + p + 1];
            const float rdet = 1.0f / (a * dd - bb * cc);
            const int aw = 46 - 2 * rd;
            const int cb = p + 2;
            const int tot = OD * aw;
            for (int e = tid; e < tot; e += 256) {
                int rr = e / aw;
                int c = cb + (e - rr * aw);
                float rp = cu[p * 49 + c];
                float rq = cu[(p + 1) * 49 + c];
                float np = (dd * rp - bb * rq) * rdet;
                float nq = (a * rq - cc * rp) * rdet;
                float val;
                if (rr == p)          val = np;
                else if (rr == p + 1) val = nq;
                else                  val = cu[rr * 49 + c] - cu[rr * 49 + p] * np - cu[rr * 49 + p + 1] * nq;
                nx[rr * 49 + c] = val;
            }
            __syncthreads();
        }

        bool okl = true;
        #pragma unroll
        for (int s = 0; s < 2; s++) {
            int e = tid + s * 256;
            int o = e >> 5, i = e & 31;
            float kv = augA[o * 49 + 16 + i];
            g_W[t][(SD + o) * SD + i] = kv;
            float pv = KPrev[e];
            KPrev[e] = kv;
            if (fabsf(kv - pv) >= 3e-6f) okl = false;
        }

        {
            const int i = lane, jg = wid;
            float w0 = FT[jg * P32 + i];
            float w1 = FT[(jg + 8) * P32 + i];
            float w2 = FT[(jg + 16) * P32 + i];
            float w3 = FT[(jg + 24) * P32 + i];
            #pragma unroll
            for (int o = 0; o < OD; o++) {
                float kv = augA[o * 49 + 16 + i];
                w0 -= Greg[o * 4 + 0] * kv;
                w1 -= Greg[o * 4 + 1] * kv;
                w2 -= Greg[o * 4 + 2] * kv;
                w3 -= Greg[o * 4 + 3] * kv;
            }
            float* wt = g_W[t];
            wt[jg * SD + i]        = w0;
            wt[(jg + 8) * SD + i]  = w1;
            wt[(jg + 16) * SD + i] = w2;
            wt[(jg + 24) * SD + i] = w3;
        }

        {
            const int j = lane, ig = wid;
            float p0 = Pp[ig * P32 + j];
            float p1 = Pp[(ig + 8) * P32 + j];
            float p2 = Pp[(ig + 16) * P32 + j];
            float p3 = Pp[(ig + 24) * P32 + j];
            #pragma unroll
            for (int o = 0; o < OD; o++) {
                float hv = HPs[o * P32 + j];
                p0 -= augA[o * 49 + 16 + ig] * hv;
                p1 -= augA[o * 49 + 16 + ig + 8] * hv;
                p2 -= augA[o * 49 + 16 + ig + 16] * hv;
                p3 -= augA[o * 49 + 16 + ig + 24] * hv;
            }
            Ps[ig * P32 + j]        = p0;
            Ps[(ig + 8) * P32 + j]  = p1;
            Ps[(ig + 16) * P32 + j] = p2;
            Ps[(ig + 24) * P32 + j] = p3;
        }

        int conv = __syncthreads_and((int)(okl && (t > 0)));
        if (conv) {
            if (tid == 0) g_tconv = t;
            break;
        }
    }
}

// ---------------------------------------------------------------------------
// FALLBACK phase 2 (verified) — no-op if g_special.
// ---------------------------------------------------------------------------
__global__ void __launch_bounds__(256, 1) phase2_kernel(
    const float* __restrict__ x0g,
    const float* __restrict__ meas,
    float* __restrict__ out)
{
    if (g_special) return;

    __shared__ float Wb[2][48 * SD];
    __shared__ float xs[8][2][SD + 1];
    __shared__ float zs[8][2][OD];

    const int tid  = threadIdx.x;
    const int bl   = tid >> 5;
    const int lane = tid & 31;
    const int b0   = (blockIdx.x * 8 + bl) * 2;
    const int b1   = b0 + 1;
    const int lzb  = (lane < OD) ? b0 : b1;
    const int lz   = lane & 15;
    const int tconv = g_tconv;

    xs[bl][0][lane] = x0g[b0 * SD + lane];
    xs[bl][1][lane] = x0g[b1 * SD + lane];
    zs[bl][lane >> 4][lz] = meas[(lzb * TT + 0) * OD + lz];
    {
        const float4* gw = (const float4*)g_W[0];
        float4* d = (float4*)Wb[0];
        d[tid] = gw[tid];
        if (tid < 128) d[256 + tid] = gw[256 + tid];
    }
    __syncthreads();

    int cur = 0;
    int tW = 0;

    #pragma unroll 1
    for (int t = 0; t < TT; t++) {
        int tn = (t + 1 < TT) ? ((t + 1 < tconv) ? (t + 1) : tconv) : tW;
        const bool stage = (tn != tW);

        float4 n0, n1;
        float zn;
        if (stage) {
            const float4* gw = (const float4*)g_W[tn];
            n0 = gw[tid];
            if (tid < 128) n1 = gw[256 + tid];
        }
        if (t + 1 < TT) zn = meas[(lzb * TT + (t + 1)) * OD + lz];

        const float* AT = Wb[cur];
        const float* KT = Wb[cur] + SD * SD;
        float a0 = 0.f, a1 = 0.f, c0 = 0.f, c1 = 0.f;
        #pragma unroll
        for (int j = 0; j < SD; j += 2) {
            float w0 = AT[j * SD + lane];
            float w1 = AT[(j + 1) * SD + lane];
            a0 += w0 * xs[bl][0][j];
            c0 += w0 * xs[bl][1][j];
            a1 += w1 * xs[bl][0][j + 1];
            c1 += w1 * xs[bl][1][j + 1];
        }
        #pragma unroll
        for (int o = 0; o < OD; o += 2) {
            float w0 = KT[o * SD + lane];
            float w1 = KT[(o + 1) * SD + lane];
            a0 += w0 * zs[bl][0][o];
            c0 += w0 * zs[bl][1][o];
            a1 += w1 * zs[bl][0][o + 1];
            c1 += w1 * zs[bl][1][o + 1];
        }
        const float xa = a0 + a1;
        const float xc = c0 + c1;
        out[(b0 * TT + t) * SD + lane] = xa;
        out[(b1 * TT + t) * SD + lane] = xc;
        __syncthreads();

        xs[bl][0][lane] = xa;
        xs[bl][1][lane] = xc;
        if (t + 1 < TT) zs[bl][lane >> 4][lz] = zn;
        if (stage) {
            float4* d = (float4*)Wb[cur ^ 1];
            d[tid] = n0;
            if (tid < 128) d[256 + tid] = n1;
            cur ^= 1;
            tW = tn;
        }
        __syncthreads();
    }
}

// ---------------------------------------------------------------------------
extern "C" void kernel_launch(void* const* d_in, const int* in_sizes, int n_in,
                              void* d_out, int out_size) {
    const float* state0 = (const float*)d_in[0];  // (B, 32)
    const float* cov0   = (const float*)d_in[1];  // (B, 32, 32)
    const float* meas   = (const float*)d_in[2];  // (B, 64, 16)
    const float* F      = (const float*)d_in[3];  // (32, 32)
    const float* H      = (const float*)d_in[4];  // (16, 32)
    const float* Q      = (const float*)d_in[5];  // (32, 32)
    const float* R      = (const float*)d_in[6];  // (16, 16)
    float* out = (float*)d_out;                   // (B, 64, 32)
    (void)in_sizes; (void)n_in; (void)out_size;

    const int dyn = 16 * TT * OD * (int)sizeof(float);   // 64 KB zb
    cudaFuncSetAttribute(fused_kernel,
                         cudaFuncAttributeMaxDynamicSharedMemorySize, dyn);

    fused_kernel<<<NB / 16, 512, dyn>>>(state0, meas, out, F, H, Q, R, cov0);
    phase1_kernel<<<1, 256>>>(F, H, Q, R, cov0);        // no-op if special
    phase2_kernel<<<NB / 16, 256>>>(state0, meas, out); // no-op if special
}